// round 1
// baseline (speedup 1.0000x reference)
#include <cuda_runtime.h>
#include <math.h>
#include <stdint.h>

#define NROWS 8192
#define TT    60
#define DF    6
#define HH    64
#define GG    256
#define RB    64
#define NTHR  256

// -------- device scratch (static globals; no runtime allocation) --------
__device__ float g_hs0[(size_t)NROWS * TT * HH];   // layer-0 hidden sequence
__device__ float g_hlast[NROWS * HH];              // layer-1 final hidden
__device__ float g_s1[NROWS];
__device__ float g_s2[NROWS];
__device__ float g_v1[HH];
__device__ float g_v2[HH];
__device__ float g_c12[2];
__device__ float g_smax;

// -------- packed fp32x2 FMA (Blackwell FFMA2) --------
__device__ __forceinline__ void fma2(float2& d, float2 a, float2 b) {
    asm("fma.rn.f32x2 %0, %1, %2, %0;"
        : "+l"(*reinterpret_cast<unsigned long long*>(&d))
        : "l"(*reinterpret_cast<unsigned long long*>(&a)),
          "l"(*reinterpret_cast<unsigned long long*>(&b)));
}

__device__ __forceinline__ float sigf(float x) {
    return __fdividef(1.f, 1.f + __expf(-x));
}
__device__ __forceinline__ float tanhfast(float x) {
    return 1.f - __fdividef(2.f, __expf(2.f * x) + 1.f);
}

// =======================================================================
// LSTM layer kernel: 64 rows / block, 256 threads.
// Thread (tx,ty): rows ty*8..ty*8+7 (4 row-pairs, f32x2), gates {tx,tx+32}x{i,f,g,o}.
// sW* stored transposed [k][g]; sH/sX stored [k][row] with pitch 66.
// =======================================================================
__device__ __forceinline__ void gemm_acc(float2 (&acc)[4][8], const float* __restrict__ sW,
                                         const float* __restrict__ sXv, int K, int rloc,
                                         const int (&gofs)[8]) {
    #pragma unroll 4
    for (int k = 0; k < K; ++k) {
        float2 h2[4];
        #pragma unroll
        for (int rp = 0; rp < 4; ++rp)
            h2[rp] = *(const float2*)&sXv[k * 66 + rloc + rp * 2];
        #pragma unroll
        for (int s = 0; s < 8; ++s) {
            float w = sW[k * 256 + gofs[s]];
            float2 w2 = make_float2(w, w);
            #pragma unroll
            for (int rp = 0; rp < 4; ++rp) fma2(acc[rp][s], h2[rp], w2);
        }
    }
}

template <int FEAT, int LAYER>
__global__ void __launch_bounds__(NTHR, 1)
lstm_kernel(const float* __restrict__ xin_param,
            const float* __restrict__ Wih, const float* __restrict__ Whh,
            const float* __restrict__ bih, const float* __restrict__ bhh) {
    extern __shared__ float sm[];
    float* sWh = sm;                 // 64*256
    float* sH  = sWh + 64 * 256;     // 64*66
    float* sX  = sH + 64 * 66;       // 64*66 (FEAT rows used)
    float* sB  = sX + 64 * 66;       // 256
    float* sWx = sB + 256;           // FEAT*256

    const float* xin = (LAYER == 0) ? xin_param : g_hs0;
    const int tid = threadIdx.x;
    const int tx = tid & 31, ty = tid >> 5;
    const int rowbase = blockIdx.x * RB;
    const int rloc = ty * 8;

    // stage weights (transposed) + bias
    for (int idx = tid; idx < 64 * 256; idx += NTHR) {
        int g = idx >> 6, k = idx & 63;
        sWh[k * 256 + g] = Whh[idx];
    }
    for (int idx = tid; idx < FEAT * 256; idx += NTHR) {
        int g = idx / FEAT, d = idx - g * FEAT;
        sWx[d * 256 + g] = Wih[idx];
    }
    for (int g = tid; g < 256; g += NTHR) sB[g] = bih[g] + bhh[g];
    __syncthreads();

    int gofs[8];
    float bv[8];
    #pragma unroll
    for (int s = 0; s < 8; ++s) {
        int gt = s >> 1, jj = s & 1;
        gofs[s] = gt * 64 + jj * 32 + tx;
        bv[s] = sB[gofs[s]];
    }

    float2 creg[4][2];
    #pragma unroll
    for (int rp = 0; rp < 4; ++rp)
        #pragma unroll
        for (int jj = 0; jj < 2; ++jj) creg[rp][jj] = make_float2(0.f, 0.f);

    #pragma unroll 1
    for (int t = 0; t < TT; ++t) {
        // load x_t (transposed into [d][row])
        for (int idx = tid; idx < FEAT * RB; idx += NTHR) {
            int r = idx / FEAT, d = idx - r * FEAT;
            sX[d * 66 + r] = xin[((size_t)(rowbase + r) * TT + t) * FEAT + d];
        }
        __syncthreads();  // sX ready; prev step's sH writes visible

        float2 acc[4][8];
        #pragma unroll
        for (int rp = 0; rp < 4; ++rp)
            #pragma unroll
            for (int s = 0; s < 8; ++s) acc[rp][s] = make_float2(bv[s], bv[s]);

        if (t > 0) gemm_acc(acc, sWh, sH, 64, rloc, gofs);
        gemm_acc(acc, sWx, sX, FEAT, rloc, gofs);

        __syncthreads();  // all GEMM reads of sH/sX done before rewriting sH

        // LSTM cell update; slots: i=s(0+jj), f=s(2+jj), g=s(4+jj), o=s(6+jj)
        #pragma unroll
        for (int rp = 0; rp < 4; ++rp) {
            #pragma unroll
            for (int jj = 0; jj < 2; ++jj) {
                float2 iv = acc[rp][0 + jj], fv = acc[rp][2 + jj];
                float2 gv = acc[rp][4 + jj], ov = acc[rp][6 + jj];
                float2 cv = creg[rp][jj];
                float2 hv;
                cv.x = sigf(fv.x) * cv.x + sigf(iv.x) * tanhfast(gv.x);
                hv.x = sigf(ov.x) * tanhfast(cv.x);
                cv.y = sigf(fv.y) * cv.y + sigf(iv.y) * tanhfast(gv.y);
                hv.y = sigf(ov.y) * tanhfast(cv.y);
                creg[rp][jj] = cv;
                int j = jj * 32 + tx;
                *(float2*)&sH[j * 66 + rloc + rp * 2] = hv;
                int r = rowbase + rloc + rp * 2;
                if (LAYER == 0) {
                    g_hs0[((size_t)r * TT + t) * HH + j] = hv.x;
                    g_hs0[((size_t)(r + 1) * TT + t) * HH + j] = hv.y;
                } else if (t == TT - 1) {
                    g_hlast[r * HH + j] = hv.x;
                    g_hlast[(r + 1) * HH + j] = hv.y;
                }
            }
        }
    }
}

// =======================================================================
// GAT preparation kernels
// =======================================================================
// v1 = Wt^T a[:64], v2 = Wt^T a[64:], c1 = bt.a[:64], c2 = bt.a[64:]
__global__ void prep1(const float* __restrict__ Wt, const float* __restrict__ bt,
                      const float* __restrict__ a) {
    int tid = threadIdx.x;
    if (tid < 64) {
        float v = 0.f;
        for (int g = 0; g < 64; ++g) v += Wt[g * 64 + tid] * a[g];
        g_v1[tid] = v;
    } else if (tid < 128) {
        int k = tid - 64;
        float v = 0.f;
        for (int g = 0; g < 64; ++g) v += Wt[g * 64 + k] * a[64 + g];
        g_v2[k] = v;
    }
    if (tid == 0) {
        float c = 0.f;
        for (int g = 0; g < 64; ++g) c += bt[g] * a[g];
        g_c12[0] = c;
    }
    if (tid == 1) {
        float c = 0.f;
        for (int g = 0; g < 64; ++g) c += bt[g] * a[64 + g];
        g_c12[1] = c;
    }
}

// s1[i] = last[i].v1 + c1 ; s2[i] = last[i].v2 + c2   (warp per row)
__global__ void prep2() {
    int lane = threadIdx.x & 31, w = threadIdx.x >> 5;
    int r = blockIdx.x * 8 + w;
    float l0 = g_hlast[r * 64 + lane], l1 = g_hlast[r * 64 + 32 + lane];
    float p1 = l0 * g_v1[lane] + l1 * g_v1[lane + 32];
    float p2 = l0 * g_v2[lane] + l1 * g_v2[lane + 32];
    #pragma unroll
    for (int o = 16; o; o >>= 1) {
        p1 += __shfl_xor_sync(0xffffffffu, p1, o);
        p2 += __shfl_xor_sync(0xffffffffu, p2, o);
    }
    if (lane == 0) {
        g_s1[r] = p1 + g_c12[0];
        g_s2[r] = p2 + g_c12[1];
    }
}

// global max of s1 (lrelu monotone => row max of scores is lrelu(s2[i]+max s1))
__global__ void prep3() {
    __shared__ float red[1024];
    int tid = threadIdx.x;
    float m = -3.4e38f;
    for (int i = tid; i < NROWS; i += 1024) m = fmaxf(m, g_s1[i]);
    red[tid] = m;
    __syncthreads();
    for (int s = 512; s; s >>= 1) {
        if (tid < s) red[tid] = fmaxf(red[tid], red[tid + s]);
        __syncthreads();
    }
    if (tid == 0) g_smax = red[0];
}

// =======================================================================
// Fused GAT + residual + FC + output head. 64 rows / block, 128 blocks.
// Flash-style over j tiles of 64; w tile in SMEM; f32x2 accumulation over rows.
// =======================================================================
__global__ void __launch_bounds__(NTHR, 1)
gat_kernel(const float* __restrict__ Wfc, const float* __restrict__ bfc,
           const float* __restrict__ Wout, const float* __restrict__ bout,
           float* __restrict__ out) {
    extern __shared__ float sm[];
    float* sV   = sm;            // 4096  : last[j-tile][64]
    float* sWt  = sV + 4096;     // 4224  : w[jl][row], pitch 66
    float* sWfc = sWt + 4224;    // 4096
    float* sZ   = sWfc + 4096;   // 4160  : fc input, pitch 65
    float* sS1  = sZ + 4160;     // 64
    float* sS2  = sS1 + 64;      // 64
    float* sM   = sS2 + 64;      // 64
    float* sSum = sM + 64;       // 64
    float* sWo  = sSum + 64;     // 64
    float* sBfc = sWo + 64;      // 64
    float* sRed = sBfc + 64;     // 256

    const int tid = threadIdx.x;
    const int tx = tid & 31, ty = tid >> 5;
    const int rowbase = blockIdx.x * 64;

    for (int idx = tid; idx < 4096; idx += NTHR) sWfc[idx] = Wfc[idx];
    if (tid < 64) {
        sWo[tid] = Wout[tid];
        sBfc[tid] = bfc[tid];
        float s2v = g_s2[rowbase + tid];
        sS2[tid] = s2v;
        float mv = s2v + g_smax;
        sM[tid] = mv > 0.f ? mv : 0.01f * mv;
    }
    float2 acc[4][2];
    #pragma unroll
    for (int rp = 0; rp < 4; ++rp) {
        acc[rp][0] = make_float2(0.f, 0.f);
        acc[rp][1] = make_float2(0.f, 0.f);
    }
    float psum = 0.f;
    __syncthreads();

    for (int jt = 0; jt < NROWS / 64; ++jt) {
        for (int idx = tid; idx < 4096; idx += NTHR)
            sV[idx] = g_hlast[jt * 4096 + idx];
        if (tid < 64) sS1[tid] = g_s1[jt * 64 + tid];
        __syncthreads();

        // phase A: w[jl][i] = exp(lrelu(s2[i]+s1[j]) - M[i]); row-partial sums
        {
            int ai = tid & 63, aq = tid >> 6;
            float s2i = sS2[ai], mi = sM[ai];
            #pragma unroll
            for (int q = 0; q < 16; ++q) {
                int jl = aq * 16 + q;
                float v = s2i + sS1[jl];
                v = v > 0.f ? v : 0.01f * v;
                float w = __expf(v - mi);
                sWt[jl * 66 + ai] = w;
                psum += w;
            }
        }
        __syncthreads();

        // phase B: acc[rows x cols] += w[rows] * last[j][cols]
        #pragma unroll 4
        for (int jl = 0; jl < 64; ++jl) {
            float2 w2[4];
            #pragma unroll
            for (int rp = 0; rp < 4; ++rp)
                w2[rp] = *(const float2*)&sWt[jl * 66 + ty * 8 + rp * 2];
            float va = sV[jl * 64 + tx], vb = sV[jl * 64 + tx + 32];
            float2 va2 = make_float2(va, va), vb2 = make_float2(vb, vb);
            #pragma unroll
            for (int rp = 0; rp < 4; ++rp) {
                fma2(acc[rp][0], w2[rp], va2);
                fma2(acc[rp][1], w2[rp], vb2);
            }
        }
        __syncthreads();
    }

    // reduce row sums (4 partials per row: tid, tid+64, tid+128, tid+192)
    sRed[tid] = psum;
    __syncthreads();
    if (tid < 64)
        sSum[tid] = __fdividef(1.f, sRed[tid] + sRed[tid + 64] + sRed[tid + 128] + sRed[tid + 192]);
    __syncthreads();

    // z = att@last + last  (residual)
    #pragma unroll
    for (int rp = 0; rp < 4; ++rp) {
        int r = ty * 8 + rp * 2;
        float ra = sSum[r], rb = sSum[r + 1];
        sZ[r * 65 + tx]            = acc[rp][0].x * ra + g_hlast[(rowbase + r) * 64 + tx];
        sZ[(r + 1) * 65 + tx]      = acc[rp][0].y * rb + g_hlast[(rowbase + r + 1) * 64 + tx];
        sZ[r * 65 + tx + 32]       = acc[rp][1].x * ra + g_hlast[(rowbase + r) * 64 + tx + 32];
        sZ[(r + 1) * 65 + tx + 32] = acc[rp][1].y * rb + g_hlast[(rowbase + r + 1) * 64 + tx + 32];
    }
    __syncthreads();

    // FC (lrelu) + output dot
    {
        int fi = tid & 63, fq = tid >> 6;
        float yp = 0.f;
        #pragma unroll 4
        for (int q = 0; q < 16; ++q) {
            int c = fq * 16 + q;
            float dot = sBfc[c];
            #pragma unroll 16
            for (int k = 0; k < 64; ++k) dot += sZ[fi * 65 + k] * sWfc[c * 64 + k];
            dot = dot > 0.f ? dot : 0.01f * dot;
            yp += dot * sWo[c];
        }
        sRed[tid] = yp;
    }
    __syncthreads();
    if (tid < 64)
        out[rowbase + tid] =
            sRed[tid] + sRed[tid + 64] + sRed[tid + 128] + sRed[tid + 192] + bout[0];
}

// =======================================================================
extern "C" void kernel_launch(void* const* d_in, const int* in_sizes, int n_in,
                              void* d_out, int out_size) {
    const float* x    = (const float*)d_in[0];
    const float* Wih0 = (const float*)d_in[1];
    const float* Whh0 = (const float*)d_in[2];
    const float* bih0 = (const float*)d_in[3];
    const float* bhh0 = (const float*)d_in[4];
    const float* Wih1 = (const float*)d_in[5];
    const float* Whh1 = (const float*)d_in[6];
    const float* bih1 = (const float*)d_in[7];
    const float* bhh1 = (const float*)d_in[8];
    const float* Wt   = (const float*)d_in[9];
    const float* bt   = (const float*)d_in[10];
    const float* a    = (const float*)d_in[11];
    const float* Wfc  = (const float*)d_in[12];
    const float* bfc  = (const float*)d_in[13];
    const float* Wout = (const float*)d_in[14];
    const float* bout = (const float*)d_in[15];
    float* out = (float*)d_out;

    const int SM_L0  = (16384 + 4224 + 4224 + 256 + DF * 256) * 4;
    const int SM_L1  = (16384 + 4224 + 4224 + 256 + 64 * 256) * 4;
    const int SM_GAT = (4096 + 4224 + 4096 + 4160 + 64 * 6 + 256) * 4;

    cudaFuncSetAttribute(lstm_kernel<DF, 0>, cudaFuncAttributeMaxDynamicSharedMemorySize, SM_L0);
    cudaFuncSetAttribute(lstm_kernel<HH, 1>, cudaFuncAttributeMaxDynamicSharedMemorySize, SM_L1);
    cudaFuncSetAttribute(gat_kernel, cudaFuncAttributeMaxDynamicSharedMemorySize, SM_GAT);

    lstm_kernel<DF, 0><<<NROWS / RB, NTHR, SM_L0>>>(x, Wih0, Whh0, bih0, bhh0);
    lstm_kernel<HH, 1><<<NROWS / RB, NTHR, SM_L1>>>(x, Wih1, Whh1, bih1, bhh1);
    prep1<<<1, 128>>>(Wt, bt, a);
    prep2<<<NROWS / 8, 256>>>();
    prep3<<<1, 1024>>>();
    gat_kernel<<<NROWS / 64, NTHR, SM_GAT>>>(Wfc, bfc, Wout, bout, out);
}

// round 2
// speedup vs baseline: 1.2057x; 1.2057x over previous
#include <cuda_runtime.h>
#include <math.h>
#include <stdint.h>

#define NROWS 8192
#define TT    60
#define HH    64
#define NCHUNK 128    // 8192 / 64

// -------- device scratch (static globals; no runtime allocation) --------
__device__ float g_hs0[(size_t)NROWS * TT * HH];   // layer-0 hidden sequence
__device__ float g_hlast[NROWS * HH];              // layer-1 final hidden
__device__ float g_s1[NROWS];
__device__ float g_s2[NROWS];
__device__ float g_v1[HH];
__device__ float g_v2[HH];
__device__ float g_c12[2];
__device__ float g_s1sorted[NROWS];
__device__ int   g_sidx[NROWS];
__device__ float g_A[NROWS];
__device__ float g_B[NROWS];
__device__ float g_chunkA[NCHUNK * 65];
__device__ float g_chunkB[NCHUNK * 65];
__device__ float g_preB[(size_t)(NROWS + 1) * 65];   // prefix of B*[x,1]
__device__ float g_suffA[(size_t)(NROWS + 1) * 65];  // suffix of A*[x,1]

// -------- packed fp32x2 FMA (Blackwell FFMA2) --------
__device__ __forceinline__ void fma2(float2& d, float2 a, float2 b) {
    asm("fma.rn.f32x2 %0, %1, %2, %0;"
        : "+l"(*reinterpret_cast<unsigned long long*>(&d))
        : "l"(*reinterpret_cast<unsigned long long*>(&a)),
          "l"(*reinterpret_cast<unsigned long long*>(&b)));
}

__device__ __forceinline__ float sigf(float x) {
    return __fdividef(1.f, 1.f + __expf(-x));
}
__device__ __forceinline__ float tanhfast(float x) {
    return 1.f - __fdividef(2.f, __expf(2.f * x) + 1.f);
}

// =======================================================================
// LSTM layer kernel: 64 rows / block, 512 threads (16 warps).
// Thread (tx,ty): rows ty*4 .. ty*4+3 (2 row-pairs via f32x2),
// gates {tx, tx+32} x {i,f,g,o}. Weights transposed in SMEM [k][g].
// x_t for step t+1 prefetched into registers during step-t GEMM.
// =======================================================================
template <int FEAT>
__device__ __forceinline__ void gemm_acc(float2 (&acc)[2][8], const float* __restrict__ sW,
                                         const float* __restrict__ sXv, int K, int rloc,
                                         const int (&gofs)[8]) {
    #pragma unroll 4
    for (int k = 0; k < K; ++k) {
        float2 h0 = *(const float2*)&sXv[k * 66 + rloc];
        float2 h1 = *(const float2*)&sXv[k * 66 + rloc + 2];
        #pragma unroll
        for (int s = 0; s < 8; ++s) {
            float w = sW[k * 256 + gofs[s]];
            float2 w2 = make_float2(w, w);
            fma2(acc[0][s], h0, w2);
            fma2(acc[1][s], h1, w2);
        }
    }
}

template <int FEAT, int LAYER>
__global__ void __launch_bounds__(512, 1)
lstm_kernel(const float* __restrict__ xin_param,
            const float* __restrict__ Wih, const float* __restrict__ Whh,
            const float* __restrict__ bih, const float* __restrict__ bhh) {
    extern __shared__ float sm[];
    float* sWh = sm;                    // 64*256
    float* sWx = sWh + 64 * 256;        // FEAT*256
    float* sB  = sWx + FEAT * 256;      // 256
    float* sH  = sB + 256;              // 64*66
    float* sX0 = sH + 64 * 66;          // FEAT*66
    float* sX1 = sX0 + FEAT * 66;       // FEAT*66

    const float* xin = (LAYER == 0) ? xin_param : g_hs0;
    const int tid = threadIdx.x;
    const int tx = tid & 31, ty = tid >> 5;
    const int rowbase = blockIdx.x * 64;
    const int rloc = ty * 4;

    // stage weights (transposed) + bias
    for (int idx = tid; idx < 64 * 256; idx += 512) {
        int g = idx >> 6, k = idx & 63;
        sWh[k * 256 + g] = Whh[idx];
    }
    for (int idx = tid; idx < FEAT * 256; idx += 512) {
        int g = idx / FEAT, d = idx - g * FEAT;
        sWx[d * 256 + g] = Wih[idx];
    }
    for (int g = tid; g < 256; g += 512) sB[g] = bih[g] + bhh[g];
    __syncthreads();

    int gofs[8];
    float bv[8];
    #pragma unroll
    for (int s = 0; s < 8; ++s) {
        int gt = s >> 1, jj = s & 1;
        gofs[s] = gt * 64 + jj * 32 + tx;
        bv[s] = sB[gofs[s]];
    }

    float2 creg[2][2];
    creg[0][0] = creg[0][1] = creg[1][0] = creg[1][1] = make_float2(0.f, 0.f);

    float xr[8];

    auto loadx = [&](int t) {
        if (FEAT == 64) {
            int r = tid >> 3, dbase = (tid & 7) * 8;
            const float* p = &xin[((size_t)(rowbase + r) * TT + t) * 64 + dbase];
            #pragma unroll
            for (int q = 0; q < 8; ++q) xr[q] = p[q];
        } else {
            if (tid < FEAT * 64) {
                int r = tid / FEAT, d = tid - r * FEAT;
                xr[0] = xin[((size_t)(rowbase + r) * TT + t) * FEAT + d];
            }
        }
    };
    auto storex = [&](float* sX) {
        if (FEAT == 64) {
            int r = tid >> 3, dbase = (tid & 7) * 8;
            #pragma unroll
            for (int q = 0; q < 8; ++q) sX[(dbase + q) * 66 + r] = xr[q];
        } else {
            if (tid < FEAT * 64) {
                int r = tid / FEAT, d = tid - r * FEAT;
                sX[d * 66 + r] = xr[0];
            }
        }
    };

    loadx(0);
    storex(sX0);
    __syncthreads();
    const float* sXcur = sX0;
    float* sXnxt = sX1;

    #pragma unroll 1
    for (int t = 0; t < TT; ++t) {
        if (t < TT - 1) loadx(t + 1);  // LDG overlapped with GEMM below

        float2 acc[2][8];
        #pragma unroll
        for (int rp = 0; rp < 2; ++rp)
            #pragma unroll
            for (int s = 0; s < 8; ++s) acc[rp][s] = make_float2(bv[s], bv[s]);

        if (t > 0) gemm_acc<FEAT>(acc, sWh, sH, 64, rloc, gofs);
        gemm_acc<FEAT>(acc, sWx, sXcur, FEAT, rloc, gofs);

        __syncthreads();  // GEMM reads of sH/sXcur complete

        if (t < TT - 1) storex(sXnxt);

        // cell update; slots: i=acc[rp][0+jj], f=[2+jj], g=[4+jj], o=[6+jj]
        #pragma unroll
        for (int rp = 0; rp < 2; ++rp) {
            #pragma unroll
            for (int jj = 0; jj < 2; ++jj) {
                float2 iv = acc[rp][0 + jj], fv = acc[rp][2 + jj];
                float2 gv = acc[rp][4 + jj], ov = acc[rp][6 + jj];
                float2 cv = creg[rp][jj];
                float2 hv;
                cv.x = sigf(fv.x) * cv.x + sigf(iv.x) * tanhfast(gv.x);
                hv.x = sigf(ov.x) * tanhfast(cv.x);
                cv.y = sigf(fv.y) * cv.y + sigf(iv.y) * tanhfast(gv.y);
                hv.y = sigf(ov.y) * tanhfast(cv.y);
                creg[rp][jj] = cv;
                int j = jj * 32 + tx;
                *(float2*)&sH[j * 66 + rloc + rp * 2] = hv;
                int r = rowbase + rloc + rp * 2;
                if (LAYER == 0) {
                    g_hs0[((size_t)r * TT + t) * HH + j] = hv.x;
                    g_hs0[((size_t)(r + 1) * TT + t) * HH + j] = hv.y;
                } else if (t == TT - 1) {
                    g_hlast[r * HH + j] = hv.x;
                    g_hlast[(r + 1) * HH + j] = hv.y;
                }
            }
        }
        __syncthreads();  // sH(t) + sXnxt ready for step t+1
        const float* tmp = sXcur;
        sXcur = sXnxt;
        sXnxt = (float*)tmp;
    }
}

// =======================================================================
// GAT prep
// =======================================================================
__global__ void prep1(const float* __restrict__ Wt, const float* __restrict__ bt,
                      const float* __restrict__ a) {
    int tid = threadIdx.x;
    if (tid < 64) {
        float v = 0.f;
        for (int g = 0; g < 64; ++g) v += Wt[g * 64 + tid] * a[g];
        g_v1[tid] = v;
    } else if (tid < 128) {
        int k = tid - 64;
        float v = 0.f;
        for (int g = 0; g < 64; ++g) v += Wt[g * 64 + k] * a[64 + g];
        g_v2[k] = v;
    }
    if (tid == 0) {
        float c = 0.f;
        for (int g = 0; g < 64; ++g) c += bt[g] * a[g];
        g_c12[0] = c;
    }
    if (tid == 1) {
        float c = 0.f;
        for (int g = 0; g < 64; ++g) c += bt[g] * a[64 + g];
        g_c12[1] = c;
    }
}

__global__ void prep2() {
    int lane = threadIdx.x & 31, w = threadIdx.x >> 5;
    int r = blockIdx.x * 8 + w;
    float l0 = g_hlast[r * 64 + lane], l1 = g_hlast[r * 64 + 32 + lane];
    float p1 = l0 * g_v1[lane] + l1 * g_v1[lane + 32];
    float p2 = l0 * g_v2[lane] + l1 * g_v2[lane + 32];
    #pragma unroll
    for (int o = 16; o; o >>= 1) {
        p1 += __shfl_xor_sync(0xffffffffu, p1, o);
        p2 += __shfl_xor_sync(0xffffffffu, p2, o);
    }
    if (lane == 0) {
        g_s1[r] = p1 + g_c12[0];
        g_s2[r] = p2 + g_c12[1];
    }
}

// single-block bitonic sort of (s1, idx), ascending
__global__ void __launch_bounds__(1024, 1) sort_kernel() {
    extern __shared__ char sraw[];
    float* k = (float*)sraw;
    int* v = (int*)(sraw + NROWS * 4);
    int tid = threadIdx.x;
    for (int i = tid; i < NROWS; i += 1024) {
        k[i] = g_s1[i];
        v[i] = i;
    }
    for (int size = 2; size <= NROWS; size <<= 1) {
        for (int stride = size >> 1; stride > 0; stride >>= 1) {
            __syncthreads();
            #pragma unroll
            for (int e = 0; e < NROWS / 1024; ++e) {
                int i = e * 1024 + tid;
                int j = i ^ stride;
                if (j > i) {
                    bool up = ((i & size) == 0);
                    float ki = k[i], kj = k[j];
                    if ((ki > kj) == up) {
                        k[i] = kj; k[j] = ki;
                        int t = v[i]; v[i] = v[j]; v[j] = t;
                    }
                }
            }
        }
    }
    __syncthreads();
    for (int i = tid; i < NROWS; i += 1024) {
        g_s1sorted[i] = k[i];
        g_sidx[i] = v[i];
    }
}

// per-chunk sums of A_j*[x_j,1] and B_j*[x_j,1]  (65 dims; dim 64 = denominator)
__global__ void scan1() {
    __shared__ float sA[64], sB[64];
    __shared__ int sI[64];
    int c = blockIdx.x, tid = threadIdx.x;
    if (tid < 64) {
        float smax = g_s1sorted[NROWS - 1];
        float key = g_s1sorted[c * 64 + tid];
        float A = __expf(key - smax);
        float B = __expf(0.01f * (key - smax));
        sA[tid] = A; sB[tid] = B;
        sI[tid] = g_sidx[c * 64 + tid];
        g_A[c * 64 + tid] = A;
        g_B[c * 64 + tid] = B;
    }
    __syncthreads();
    if (tid <= 64) {
        float sa = 0.f, sb = 0.f;
        #pragma unroll 4
        for (int m = 0; m < 64; ++m) {
            float xv = (tid < 64) ? g_hlast[sI[m] * 64 + tid] : 1.f;
            sa += sA[m] * xv;
            sb += sB[m] * xv;
        }
        g_chunkA[c * 65 + tid] = sa;
        g_chunkB[c * 65 + tid] = sb;
    }
}

// in-place exclusive scans of chunk sums: B forward, A reverse
__global__ void scan2() {
    int d = threadIdx.x;
    if (d <= 64) {
        float run = 0.f;
        #pragma unroll 4
        for (int c = 0; c < NCHUNK; ++c) {
            float t = g_chunkB[c * 65 + d];
            g_chunkB[c * 65 + d] = run;
            run += t;
        }
        float runA = 0.f;
        #pragma unroll 4
        for (int c = NCHUNK - 1; c >= 0; --c) {
            float t = g_chunkA[c * 65 + d];
            g_chunkA[c * 65 + d] = runA;
            runA += t;
        }
    }
}

// full prefix/suffix arrays
__global__ void scan3() {
    __shared__ float sA[64], sB[64];
    __shared__ int sI[64];
    int c = blockIdx.x, tid = threadIdx.x;
    if (tid < 64) {
        sA[tid] = g_A[c * 64 + tid];
        sB[tid] = g_B[c * 64 + tid];
        sI[tid] = g_sidx[c * 64 + tid];
    }
    __syncthreads();
    if (tid <= 64) {
        int d = tid;
        float run = g_chunkB[c * 65 + d];
        #pragma unroll 4
        for (int m = 0; m < 64; ++m) {
            size_t kk = (size_t)(c * 64 + m);
            g_preB[kk * 65 + d] = run;
            float xv = (d < 64) ? g_hlast[sI[m] * 64 + d] : 1.f;
            run += sB[m] * xv;
        }
        if (c == NCHUNK - 1) g_preB[(size_t)NROWS * 65 + d] = run;
        float runA = g_chunkA[c * 65 + d];
        #pragma unroll 4
        for (int m = 63; m >= 0; --m) {
            float xv = (d < 64) ? g_hlast[sI[m] * 64 + d] : 1.f;
            runA += sA[m] * xv;
            g_suffA[(size_t)(c * 64 + m) * 65 + d] = runA;
        }
        if (c == NCHUNK - 1) g_suffA[(size_t)NROWS * 65 + d] = 0.f;
    }
}

// =======================================================================
// Final: per row i — binary search kink, combine prefix/suffix, residual,
// FC + lrelu + output dot. One warp per row, 8 warps / block.
// =======================================================================
__global__ void __launch_bounds__(256)
final_kernel(const float* __restrict__ Wfc, const float* __restrict__ bfc,
             const float* __restrict__ Wout, const float* __restrict__ bout,
             float* __restrict__ out) {
    __shared__ float sWfcT[64 * 65];  // [k][c]
    __shared__ float sWo[64], sBfc[64];
    __shared__ float sZ[8][64];
    int tid = threadIdx.x;
    for (int idx = tid; idx < 4096; idx += 256) {
        int cc = idx >> 6, kq = idx & 63;
        sWfcT[kq * 65 + cc] = Wfc[idx];
    }
    if (tid < 64) {
        sWo[tid] = Wout[tid];
        sBfc[tid] = bfc[tid];
    }
    __syncthreads();

    int wy = tid >> 5, l = tid & 31;
    int i = blockIdx.x * 8 + wy;
    float smax = g_s1sorted[NROWS - 1];
    float s2 = g_s2[i];
    float thr = -s2;

    int kk = 0;
    #pragma unroll
    for (int st = 4096; st > 0; st >>= 1)
        if (kk + st <= NROWS && g_s1sorted[kk + st - 1] <= thr) kk += st;

    float u = s2 + smax;
    float fA, fB;
    if (u > 0.f) { fA = 1.f;              fB = __expf(-0.99f * u); }
    else         { fA = __expf(0.99f * u); fB = 1.f; }

    const float* suff = &g_suffA[(size_t)kk * 65];
    const float* pre  = &g_preB[(size_t)kk * 65];
    float denom = fA * suff[64] + fB * pre[64];
    float inv = __fdividef(1.f, denom);
    #pragma unroll
    for (int h = 0; h < 2; ++h) {
        int d = l + h * 32;
        float num = fA * suff[d] + fB * pre[d];
        sZ[wy][d] = num * inv + g_hlast[i * 64 + d];
    }
    __syncwarp();

    float yp = 0.f;
    #pragma unroll
    for (int h = 0; h < 2; ++h) {
        int c = l + h * 32;
        float dot = sBfc[c];
        #pragma unroll 16
        for (int kq = 0; kq < 64; ++kq) dot += sZ[wy][kq] * sWfcT[kq * 65 + c];
        dot = dot > 0.f ? dot : 0.01f * dot;
        yp += dot * sWo[c];
    }
    #pragma unroll
    for (int o = 16; o; o >>= 1) yp += __shfl_xor_sync(0xffffffffu, yp, o);
    if (l == 0) out[i] = yp + bout[0];
}

// =======================================================================
extern "C" void kernel_launch(void* const* d_in, const int* in_sizes, int n_in,
                              void* d_out, int out_size) {
    const float* x    = (const float*)d_in[0];
    const float* Wih0 = (const float*)d_in[1];
    const float* Whh0 = (const float*)d_in[2];
    const float* bih0 = (const float*)d_in[3];
    const float* bhh0 = (const float*)d_in[4];
    const float* Wih1 = (const float*)d_in[5];
    const float* Whh1 = (const float*)d_in[6];
    const float* bih1 = (const float*)d_in[7];
    const float* bhh1 = (const float*)d_in[8];
    const float* Wt   = (const float*)d_in[9];
    const float* bt   = (const float*)d_in[10];
    const float* a    = (const float*)d_in[11];
    const float* Wfc  = (const float*)d_in[12];
    const float* bfc  = (const float*)d_in[13];
    const float* Wout = (const float*)d_in[14];
    const float* bout = (const float*)d_in[15];
    float* out = (float*)d_out;

    const int SM_L0 = (64 * 256 + 6 * 256 + 256 + 64 * 66 + 2 * 6 * 66) * 4;
    const int SM_L1 = (64 * 256 + 64 * 256 + 256 + 64 * 66 + 2 * 64 * 66) * 4;
    const int SM_SORT = NROWS * 8;

    cudaFuncSetAttribute(lstm_kernel<6, 0>, cudaFuncAttributeMaxDynamicSharedMemorySize, SM_L0);
    cudaFuncSetAttribute(lstm_kernel<64, 1>, cudaFuncAttributeMaxDynamicSharedMemorySize, SM_L1);
    cudaFuncSetAttribute(sort_kernel, cudaFuncAttributeMaxDynamicSharedMemorySize, SM_SORT);

    lstm_kernel<6, 0><<<NROWS / 64, 512, SM_L0>>>(x, Wih0, Whh0, bih0, bhh0);
    lstm_kernel<64, 1><<<NROWS / 64, 512, SM_L1>>>(x, Wih1, Whh1, bih1, bhh1);
    prep1<<<1, 128>>>(Wt, bt, a);
    prep2<<<NROWS / 8, 256>>>();
    sort_kernel<<<1, 1024, SM_SORT>>>();
    scan1<<<NCHUNK, 128>>>();
    scan2<<<1, 128>>>();
    scan3<<<NCHUNK, 128>>>();
    final_kernel<<<NROWS / 8, 256>>>(Wfc, bfc, Wout, bout, out);
}

// round 3
// speedup vs baseline: 1.2609x; 1.0458x over previous
#include <cuda_runtime.h>
#include <math.h>
#include <stdint.h>

#define NROWS 8192
#define TT    60
#define HH    64
#define NCHUNK 128    // 8192 / 64

// -------- device scratch (static globals; no runtime allocation) --------
__device__ float g_hs0[(size_t)NROWS * TT * HH];   // layer-0 hidden sequence
__device__ float g_hlast[NROWS * HH];              // layer-1 final hidden
__device__ float g_s1[NROWS];
__device__ float g_s2[NROWS];
__device__ float g_v1[HH];
__device__ float g_v2[HH];
__device__ float g_c12[2];
__device__ float g_s1sorted[NROWS];
__device__ int   g_sidx[NROWS];
__device__ float g_A[NROWS];
__device__ float g_B[NROWS];
__device__ float g_chunkA[NCHUNK * 65];
__device__ float g_chunkB[NCHUNK * 65];
__device__ float g_preB[(size_t)(NROWS + 1) * 65];   // prefix of B*[x,1]
__device__ float g_suffA[(size_t)(NROWS + 1) * 65];  // suffix of A*[x,1]

// -------- packed fp32x2 FMA (Blackwell FFMA2) --------
__device__ __forceinline__ void fma2(float2& d, float2 a, float2 b) {
    asm("fma.rn.f32x2 %0, %1, %2, %0;"
        : "+l"(*reinterpret_cast<unsigned long long*>(&d))
        : "l"(*reinterpret_cast<unsigned long long*>(&a)),
          "l"(*reinterpret_cast<unsigned long long*>(&b)));
}

__device__ __forceinline__ float sigf(float x) {
    return __fdividef(1.f, 1.f + __expf(-x));
}
__device__ __forceinline__ float tanhfast(float x) {
    return 1.f - __fdividef(2.f, __expf(2.f * x) + 1.f);
}

// =======================================================================
// LSTM layer: 64 rows / block, 512 threads (16 warps).
// Warp (ty,tz): ty = wid>>1 selects row-group (8 rows), tz = wid&1 selects
// j-half. Thread: j = tz*32+tx, rows rloc..rloc+7 (4 float2 row-pairs),
// 4 gate types {i,f,g,o} at gate = s*64 + j  -> cell update register-local.
// Per warp per k: 2 LDS.128 (h bcast) + 4 LDS.32 (w) + 16 FFMA2.
// Weights transposed in SMEM [k][gate]; sH/sX stored [j or d][row] pitch 72.
// =======================================================================
#define PITCH 72

__device__ __forceinline__ void gemm_acc4(float2 (&acc)[4][4], const float* __restrict__ sW,
                                          const float* __restrict__ sV, int K, int rloc,
                                          const int (&gofs)[4]) {
    #pragma unroll 4
    for (int k = 0; k < K; ++k) {
        float4 ha = *(const float4*)&sV[k * PITCH + rloc];
        float4 hb = *(const float4*)&sV[k * PITCH + rloc + 4];
        float2 h01 = make_float2(ha.x, ha.y);
        float2 h23 = make_float2(ha.z, ha.w);
        float2 h45 = make_float2(hb.x, hb.y);
        float2 h67 = make_float2(hb.z, hb.w);
        #pragma unroll
        for (int s = 0; s < 4; ++s) {
            float w = sW[k * 256 + gofs[s]];
            float2 w2 = make_float2(w, w);
            fma2(acc[0][s], h01, w2);
            fma2(acc[1][s], h23, w2);
            fma2(acc[2][s], h45, w2);
            fma2(acc[3][s], h67, w2);
        }
    }
}

template <int FEAT, int LAYER>
__global__ void __launch_bounds__(512, 1)
lstm_kernel(const float* __restrict__ xin_param,
            const float* __restrict__ Wih, const float* __restrict__ Whh,
            const float* __restrict__ bih, const float* __restrict__ bhh) {
    extern __shared__ float sm[];
    float* sWh = sm;                     // 64*256
    float* sWx = sWh + 64 * 256;         // FEAT*256
    float* sB  = sWx + FEAT * 256;       // 256
    float* sH  = sB + 256;               // 64*PITCH
    float* sX0 = sH + 64 * PITCH;        // FEAT*PITCH
    float* sX1 = sX0 + FEAT * PITCH;     // FEAT*PITCH

    const float* xin = (LAYER == 0) ? xin_param : g_hs0;
    const int tid = threadIdx.x;
    const int tx = tid & 31;
    const int wid = tid >> 5;
    const int tz = wid & 1;
    const int ty = wid >> 1;
    const int rowbase = blockIdx.x * 64;
    const int rloc = ty * 8;
    const int j = tz * 32 + tx;

    // stage weights (transposed [k][g]) + bias
    for (int idx = tid; idx < 64 * 256; idx += 512) {
        int g = idx >> 6, k = idx & 63;
        sWh[k * 256 + g] = Whh[idx];
    }
    for (int idx = tid; idx < FEAT * 256; idx += 512) {
        int g = idx / FEAT, d = idx - g * FEAT;
        sWx[d * 256 + g] = Wih[idx];
    }
    for (int g = tid; g < 256; g += 512) sB[g] = bih[g] + bhh[g];
    __syncthreads();

    int gofs[4];
    float bv[4];
    #pragma unroll
    for (int s = 0; s < 4; ++s) {
        gofs[s] = s * 64 + j;
        bv[s] = sB[gofs[s]];
    }

    float2 creg[4];
    #pragma unroll
    for (int rp = 0; rp < 4; ++rp) creg[rp] = make_float2(0.f, 0.f);

    float xr[8];

    auto loadx = [&](int t) {
        if (FEAT == 64) {
            int r = tid >> 3, dbase = (tid & 7) * 8;
            const float* p = &xin[((size_t)(rowbase + r) * TT + t) * 64 + dbase];
            #pragma unroll
            for (int q = 0; q < 8; ++q) xr[q] = p[q];
        } else {
            if (tid < FEAT * 64) {
                int r = tid / FEAT, d = tid - r * FEAT;
                xr[0] = xin[((size_t)(rowbase + r) * TT + t) * FEAT + d];
            }
        }
    };
    auto storex = [&](float* sX) {
        if (FEAT == 64) {
            int r = tid >> 3, dbase = (tid & 7) * 8;
            #pragma unroll
            for (int q = 0; q < 8; ++q) sX[(dbase + q) * PITCH + r] = xr[q];
        } else {
            if (tid < FEAT * 64) {
                int r = tid / FEAT, d = tid - r * FEAT;
                sX[d * PITCH + r] = xr[0];
            }
        }
    };

    loadx(0);
    storex(sX0);
    __syncthreads();
    const float* sXcur = sX0;
    float* sXnxt = sX1;

    #pragma unroll 1
    for (int t = 0; t < TT; ++t) {
        if (t < TT - 1) loadx(t + 1);  // LDG overlapped with GEMM

        float2 acc[4][4];
        #pragma unroll
        for (int rp = 0; rp < 4; ++rp)
            #pragma unroll
            for (int s = 0; s < 4; ++s) acc[rp][s] = make_float2(bv[s], bv[s]);

        if (t > 0) gemm_acc4(acc, sWh, sH, 64, rloc, gofs);
        gemm_acc4(acc, sWx, sXcur, FEAT, rloc, gofs);

        __syncthreads();  // GEMM reads of sH/sXcur complete

        if (t < TT - 1) storex(sXnxt);

        // cell update (all gate types local): s0=i, s1=f, s2=g, s3=o
        float2 hv[4];
        #pragma unroll
        for (int rp = 0; rp < 4; ++rp) {
            float2 iv = acc[rp][0], fv = acc[rp][1];
            float2 gv = acc[rp][2], ov = acc[rp][3];
            float2 cv = creg[rp];
            cv.x = sigf(fv.x) * cv.x + sigf(iv.x) * tanhfast(gv.x);
            cv.y = sigf(fv.y) * cv.y + sigf(iv.y) * tanhfast(gv.y);
            hv[rp].x = sigf(ov.x) * tanhfast(cv.x);
            hv[rp].y = sigf(ov.y) * tanhfast(cv.y);
            creg[rp] = cv;
        }
        *(float4*)&sH[j * PITCH + rloc]     = make_float4(hv[0].x, hv[0].y, hv[1].x, hv[1].y);
        *(float4*)&sH[j * PITCH + rloc + 4] = make_float4(hv[2].x, hv[2].y, hv[3].x, hv[3].y);

        if (LAYER == 0) {
            #pragma unroll
            for (int rp = 0; rp < 4; ++rp) {
                int r = rowbase + rloc + rp * 2;
                g_hs0[((size_t)r * TT + t) * HH + j] = hv[rp].x;
                g_hs0[((size_t)(r + 1) * TT + t) * HH + j] = hv[rp].y;
            }
        } else if (t == TT - 1) {
            #pragma unroll
            for (int rp = 0; rp < 4; ++rp) {
                int r = rowbase + rloc + rp * 2;
                g_hlast[r * HH + j] = hv[rp].x;
                g_hlast[(r + 1) * HH + j] = hv[rp].y;
            }
        }
        __syncthreads();  // sH(t) + sXnxt ready for next step
        const float* tmp = sXcur;
        sXcur = sXnxt;
        sXnxt = (float*)tmp;
    }
}

// =======================================================================
// GAT prep
// =======================================================================
__global__ void prep1(const float* __restrict__ Wt, const float* __restrict__ bt,
                      const float* __restrict__ a) {
    int tid = threadIdx.x;
    if (tid < 64) {
        float v = 0.f;
        for (int g = 0; g < 64; ++g) v += Wt[g * 64 + tid] * a[g];
        g_v1[tid] = v;
    } else if (tid < 128) {
        int k = tid - 64;
        float v = 0.f;
        for (int g = 0; g < 64; ++g) v += Wt[g * 64 + k] * a[64 + g];
        g_v2[k] = v;
    }
    if (tid == 0) {
        float c = 0.f;
        for (int g = 0; g < 64; ++g) c += bt[g] * a[g];
        g_c12[0] = c;
    }
    if (tid == 1) {
        float c = 0.f;
        for (int g = 0; g < 64; ++g) c += bt[g] * a[64 + g];
        g_c12[1] = c;
    }
}

__global__ void prep2() {
    int lane = threadIdx.x & 31, w = threadIdx.x >> 5;
    int r = blockIdx.x * 8 + w;
    float l0 = g_hlast[r * 64 + lane], l1 = g_hlast[r * 64 + 32 + lane];
    float p1 = l0 * g_v1[lane] + l1 * g_v1[lane + 32];
    float p2 = l0 * g_v2[lane] + l1 * g_v2[lane + 32];
    #pragma unroll
    for (int o = 16; o; o >>= 1) {
        p1 += __shfl_xor_sync(0xffffffffu, p1, o);
        p2 += __shfl_xor_sync(0xffffffffu, p2, o);
    }
    if (lane == 0) {
        g_s1[r] = p1 + g_c12[0];
        g_s2[r] = p2 + g_c12[1];
    }
}

// single-block bitonic sort of (s1, idx), ascending
__global__ void __launch_bounds__(1024, 1) sort_kernel() {
    extern __shared__ char sraw[];
    float* k = (float*)sraw;
    int* v = (int*)(sraw + NROWS * 4);
    int tid = threadIdx.x;
    for (int i = tid; i < NROWS; i += 1024) {
        k[i] = g_s1[i];
        v[i] = i;
    }
    for (int size = 2; size <= NROWS; size <<= 1) {
        for (int stride = size >> 1; stride > 0; stride >>= 1) {
            __syncthreads();
            #pragma unroll
            for (int e = 0; e < NROWS / 1024; ++e) {
                int i = e * 1024 + tid;
                int j = i ^ stride;
                if (j > i) {
                    bool up = ((i & size) == 0);
                    float ki = k[i], kj = k[j];
                    if ((ki > kj) == up) {
                        k[i] = kj; k[j] = ki;
                        int t = v[i]; v[i] = v[j]; v[j] = t;
                    }
                }
            }
        }
    }
    __syncthreads();
    for (int i = tid; i < NROWS; i += 1024) {
        g_s1sorted[i] = k[i];
        g_sidx[i] = v[i];
    }
}

// per-chunk sums of A_j*[x_j,1] and B_j*[x_j,1]  (65 dims; dim 64 = denominator)
__global__ void scan1() {
    __shared__ float sA[64], sB[64];
    __shared__ int sI[64];
    int c = blockIdx.x, tid = threadIdx.x;
    if (tid < 64) {
        float smax = g_s1sorted[NROWS - 1];
        float key = g_s1sorted[c * 64 + tid];
        float A = __expf(key - smax);
        float B = __expf(0.01f * (key - smax));
        sA[tid] = A; sB[tid] = B;
        sI[tid] = g_sidx[c * 64 + tid];
        g_A[c * 64 + tid] = A;
        g_B[c * 64 + tid] = B;
    }
    __syncthreads();
    if (tid <= 64) {
        float sa = 0.f, sb = 0.f;
        #pragma unroll 4
        for (int m = 0; m < 64; ++m) {
            float xv = (tid < 64) ? g_hlast[sI[m] * 64 + tid] : 1.f;
            sa += sA[m] * xv;
            sb += sB[m] * xv;
        }
        g_chunkA[c * 65 + tid] = sa;
        g_chunkB[c * 65 + tid] = sb;
    }
}

// parallel exclusive scans of chunk sums: B forward, A reverse.
// one block per dim d (65 blocks), 128 threads (one per chunk).
__global__ void scan2() {
    __shared__ float bufB[NCHUNK], bufA[NCHUNK];
    int d = blockIdx.x;
    int c = threadIdx.x;
    float origB = g_chunkB[c * 65 + d];
    float origA = g_chunkA[c * 65 + d];
    bufB[c] = origB;
    bufA[NCHUNK - 1 - c] = origA;   // reversed for suffix scan
    __syncthreads();
    #pragma unroll
    for (int off = 1; off < NCHUNK; off <<= 1) {
        float tb = (c >= off) ? bufB[c - off] : 0.f;
        float ta = (c >= off) ? bufA[c - off] : 0.f;
        __syncthreads();
        bufB[c] += tb;
        bufA[c] += ta;
        __syncthreads();
    }
    // exclusive values
    g_chunkB[c * 65 + d] = bufB[c] - origB;
    g_chunkA[c * 65 + d] = bufA[NCHUNK - 1 - c] - origA;
}

// full prefix/suffix arrays
__global__ void scan3() {
    __shared__ float sA[64], sB[64];
    __shared__ int sI[64];
    int c = blockIdx.x, tid = threadIdx.x;
    if (tid < 64) {
        sA[tid] = g_A[c * 64 + tid];
        sB[tid] = g_B[c * 64 + tid];
        sI[tid] = g_sidx[c * 64 + tid];
    }
    __syncthreads();
    if (tid <= 64) {
        int d = tid;
        float run = g_chunkB[c * 65 + d];
        #pragma unroll 4
        for (int m = 0; m < 64; ++m) {
            size_t kk = (size_t)(c * 64 + m);
            g_preB[kk * 65 + d] = run;
            float xv = (d < 64) ? g_hlast[sI[m] * 64 + d] : 1.f;
            run += sB[m] * xv;
        }
        if (c == NCHUNK - 1) g_preB[(size_t)NROWS * 65 + d] = run;
        float runA = g_chunkA[c * 65 + d];
        #pragma unroll 4
        for (int m = 63; m >= 0; --m) {
            float xv = (d < 64) ? g_hlast[sI[m] * 64 + d] : 1.f;
            runA += sA[m] * xv;
            g_suffA[(size_t)(c * 64 + m) * 65 + d] = runA;
        }
        if (c == NCHUNK - 1) g_suffA[(size_t)NROWS * 65 + d] = 0.f;
    }
}

// =======================================================================
// Final: per row i — binary search kink, combine prefix/suffix, residual,
// FC + lrelu + output dot. One warp per row, 8 warps / block.
// =======================================================================
__global__ void __launch_bounds__(256)
final_kernel(const float* __restrict__ Wfc, const float* __restrict__ bfc,
             const float* __restrict__ Wout, const float* __restrict__ bout,
             float* __restrict__ out) {
    __shared__ float sWfcT[64 * 65];  // [k][c]
    __shared__ float sWo[64], sBfc[64];
    __shared__ float sZ[8][64];
    int tid = threadIdx.x;
    for (int idx = tid; idx < 4096; idx += 256) {
        int cc = idx >> 6, kq = idx & 63;
        sWfcT[kq * 65 + cc] = Wfc[idx];
    }
    if (tid < 64) {
        sWo[tid] = Wout[tid];
        sBfc[tid] = bfc[tid];
    }
    __syncthreads();

    int wy = tid >> 5, l = tid & 31;
    int i = blockIdx.x * 8 + wy;
    float smax = g_s1sorted[NROWS - 1];
    float s2 = g_s2[i];
    float thr = -s2;

    int kk = 0;
    #pragma unroll
    for (int st = 4096; st > 0; st >>= 1)
        if (kk + st <= NROWS && g_s1sorted[kk + st - 1] <= thr) kk += st;

    float u = s2 + smax;
    float fA, fB;
    if (u > 0.f) { fA = 1.f;               fB = __expf(-0.99f * u); }
    else         { fA = __expf(0.99f * u); fB = 1.f; }

    const float* suff = &g_suffA[(size_t)kk * 65];
    const float* pre  = &g_preB[(size_t)kk * 65];
    float denom = fA * suff[64] + fB * pre[64];
    float inv = __fdividef(1.f, denom);
    #pragma unroll
    for (int h = 0; h < 2; ++h) {
        int d = l + h * 32;
        float num = fA * suff[d] + fB * pre[d];
        sZ[wy][d] = num * inv + g_hlast[i * 64 + d];
    }
    __syncwarp();

    float yp = 0.f;
    #pragma unroll
    for (int h = 0; h < 2; ++h) {
        int c = l + h * 32;
        float dot = sBfc[c];
        #pragma unroll 16
        for (int kq = 0; kq < 64; ++kq) dot += sZ[wy][kq] * sWfcT[kq * 65 + c];
        dot = dot > 0.f ? dot : 0.01f * dot;
        yp += dot * sWo[c];
    }
    #pragma unroll
    for (int o = 16; o; o >>= 1) yp += __shfl_xor_sync(0xffffffffu, yp, o);
    if (l == 0) out[i] = yp + bout[0];
}

// =======================================================================
extern "C" void kernel_launch(void* const* d_in, const int* in_sizes, int n_in,
                              void* d_out, int out_size) {
    const float* x    = (const float*)d_in[0];
    const float* Wih0 = (const float*)d_in[1];
    const float* Whh0 = (const float*)d_in[2];
    const float* bih0 = (const float*)d_in[3];
    const float* bhh0 = (const float*)d_in[4];
    const float* Wih1 = (const float*)d_in[5];
    const float* Whh1 = (const float*)d_in[6];
    const float* bih1 = (const float*)d_in[7];
    const float* bhh1 = (const float*)d_in[8];
    const float* Wt   = (const float*)d_in[9];
    const float* bt   = (const float*)d_in[10];
    const float* a    = (const float*)d_in[11];
    const float* Wfc  = (const float*)d_in[12];
    const float* bfc  = (const float*)d_in[13];
    const float* Wout = (const float*)d_in[14];
    const float* bout = (const float*)d_in[15];
    float* out = (float*)d_out;

    const int SM_L0 = (64 * 256 + 6 * 256 + 256 + 64 * PITCH + 2 * 6 * PITCH) * 4;
    const int SM_L1 = (64 * 256 + 64 * 256 + 256 + 64 * PITCH + 2 * 64 * PITCH) * 4;
    const int SM_SORT = NROWS * 8;

    cudaFuncSetAttribute(lstm_kernel<6, 0>, cudaFuncAttributeMaxDynamicSharedMemorySize, SM_L0);
    cudaFuncSetAttribute(lstm_kernel<64, 1>, cudaFuncAttributeMaxDynamicSharedMemorySize, SM_L1);
    cudaFuncSetAttribute(sort_kernel, cudaFuncAttributeMaxDynamicSharedMemorySize, SM_SORT);

    lstm_kernel<6, 0><<<NROWS / 64, 512, SM_L0>>>(x, Wih0, Whh0, bih0, bhh0);
    lstm_kernel<64, 1><<<NROWS / 64, 512, SM_L1>>>(x, Wih1, Whh1, bih1, bhh1);
    prep1<<<1, 128>>>(Wt, bt, a);
    prep2<<<NROWS / 8, 256>>>();
    sort_kernel<<<1, 1024, SM_SORT>>>();
    scan1<<<NCHUNK, 128>>>();
    scan2<<<65, NCHUNK>>>();
    scan3<<<NCHUNK, 128>>>();
    final_kernel<<<NROWS / 8, 256>>>(Wfc, bfc, Wout, bout, out);
}

// round 4
// speedup vs baseline: 1.3280x; 1.0532x over previous
#include <cuda_runtime.h>
#include <math.h>
#include <stdint.h>

#define NROWS 8192
#define TT    60
#define HH    64
#define NCHUNK 128    // 8192 / 64

// -------- device scratch (static globals; no runtime allocation) --------
__device__ float g_hs0[(size_t)NROWS * TT * HH];   // layer-0 hidden sequence
__device__ float g_hlast[NROWS * HH];              // layer-1 final hidden
__device__ float g_s1[NROWS];
__device__ float g_s2[NROWS];
__device__ float g_v1[HH];
__device__ float g_v2[HH];
__device__ float g_c12[2];
__device__ float g_s1sorted[NROWS];
__device__ int   g_sidx[NROWS];
__device__ float g_A[NROWS];
__device__ float g_B[NROWS];
__device__ float g_chunkA[NCHUNK * 65];
__device__ float g_chunkB[NCHUNK * 65];
__device__ float g_preB[(size_t)(NROWS + 1) * 65];   // prefix of B*[x,1]
__device__ float g_suffA[(size_t)(NROWS + 1) * 65];  // suffix of A*[x,1]

// -------- packed fp32x2 FMA (Blackwell FFMA2) --------
__device__ __forceinline__ void fma2(float2& d, float2 a, float2 b) {
    asm("fma.rn.f32x2 %0, %1, %2, %0;"
        : "+l"(*reinterpret_cast<unsigned long long*>(&d))
        : "l"(*reinterpret_cast<unsigned long long*>(&a)),
          "l"(*reinterpret_cast<unsigned long long*>(&b)));
}

__device__ __forceinline__ float sigf(float x) {
    return __fdividef(1.f, 1.f + __expf(-x));
}
__device__ __forceinline__ float tanhfast(float x) {
    return 1.f - __fdividef(2.f, __expf(2.f * x) + 1.f);
}

// =======================================================================
// LSTM layer: 64 rows / block, 512 threads (16 warps).
// Warp (ty,tz): ty = wid>>1 selects row-group (8 rows), tz = wid&1 selects
// j-half. Thread: j = tz*32+tx, rows rloc..rloc+7 (4 float2 row-pairs),
// 4 gate types {i,f,g,o} at gate = s*64 + j  -> cell update register-local.
// Per warp per k: 2 LDS.128 (h bcast) + 4 LDS.32 (w) + 16 FFMA2.
// Weights transposed in SMEM [k][gate]; sH/sX stored [j or d][row] pitch 72.
// =======================================================================
#define PITCH 72

__device__ __forceinline__ void gemm_acc4(float2 (&acc)[4][4], const float* __restrict__ sW,
                                          const float* __restrict__ sV, int K, int rloc,
                                          const int (&gofs)[4]) {
    #pragma unroll 4
    for (int k = 0; k < K; ++k) {
        float4 ha = *(const float4*)&sV[k * PITCH + rloc];
        float4 hb = *(const float4*)&sV[k * PITCH + rloc + 4];
        float2 h01 = make_float2(ha.x, ha.y);
        float2 h23 = make_float2(ha.z, ha.w);
        float2 h45 = make_float2(hb.x, hb.y);
        float2 h67 = make_float2(hb.z, hb.w);
        #pragma unroll
        for (int s = 0; s < 4; ++s) {
            float w = sW[k * 256 + gofs[s]];
            float2 w2 = make_float2(w, w);
            fma2(acc[0][s], h01, w2);
            fma2(acc[1][s], h23, w2);
            fma2(acc[2][s], h45, w2);
            fma2(acc[3][s], h67, w2);
        }
    }
}

template <int FEAT, int LAYER>
__global__ void __launch_bounds__(512, 1)
lstm_kernel(const float* __restrict__ xin_param,
            const float* __restrict__ Wih, const float* __restrict__ Whh,
            const float* __restrict__ bih, const float* __restrict__ bhh) {
    extern __shared__ float sm[];
    float* sWh = sm;                     // 64*256
    float* sWx = sWh + 64 * 256;         // FEAT*256
    float* sB  = sWx + FEAT * 256;       // 256
    float* sH  = sB + 256;               // 64*PITCH
    float* sX0 = sH + 64 * PITCH;        // FEAT*PITCH
    float* sX1 = sX0 + FEAT * PITCH;     // FEAT*PITCH

    const float* xin = (LAYER == 0) ? xin_param : g_hs0;
    const int tid = threadIdx.x;
    const int tx = tid & 31;
    const int wid = tid >> 5;
    const int tz = wid & 1;
    const int ty = wid >> 1;
    const int rowbase = blockIdx.x * 64;
    const int rloc = ty * 8;
    const int j = tz * 32 + tx;

    // stage weights (transposed [k][g]) + bias
    for (int idx = tid; idx < 64 * 256; idx += 512) {
        int g = idx >> 6, k = idx & 63;
        sWh[k * 256 + g] = Whh[idx];
    }
    for (int idx = tid; idx < FEAT * 256; idx += 512) {
        int g = idx / FEAT, d = idx - g * FEAT;
        sWx[d * 256 + g] = Wih[idx];
    }
    for (int g = tid; g < 256; g += 512) sB[g] = bih[g] + bhh[g];
    __syncthreads();

    int gofs[4];
    float bv[4];
    #pragma unroll
    for (int s = 0; s < 4; ++s) {
        gofs[s] = s * 64 + j;
        bv[s] = sB[gofs[s]];
    }

    float2 creg[4];
    #pragma unroll
    for (int rp = 0; rp < 4; ++rp) creg[rp] = make_float2(0.f, 0.f);

    float xr[8];

    auto loadx = [&](int t) {
        if (FEAT == 64) {
            int r = tid >> 3, dbase = (tid & 7) * 8;
            const float* p = &xin[((size_t)(rowbase + r) * TT + t) * 64 + dbase];
            #pragma unroll
            for (int q = 0; q < 8; ++q) xr[q] = p[q];
        } else {
            if (tid < FEAT * 64) {
                int r = tid / FEAT, d = tid - r * FEAT;
                xr[0] = xin[((size_t)(rowbase + r) * TT + t) * FEAT + d];
            }
        }
    };
    auto storex = [&](float* sX) {
        if (FEAT == 64) {
            int r = tid >> 3, dbase = (tid & 7) * 8;
            #pragma unroll
            for (int q = 0; q < 8; ++q) sX[(dbase + q) * PITCH + r] = xr[q];
        } else {
            if (tid < FEAT * 64) {
                int r = tid / FEAT, d = tid - r * FEAT;
                sX[d * PITCH + r] = xr[0];
            }
        }
    };

    loadx(0);
    storex(sX0);
    __syncthreads();
    const float* sXcur = sX0;
    float* sXnxt = sX1;

    #pragma unroll 1
    for (int t = 0; t < TT; ++t) {
        if (t < TT - 1) loadx(t + 1);  // LDG overlapped with GEMM

        float2 acc[4][4];
        #pragma unroll
        for (int rp = 0; rp < 4; ++rp)
            #pragma unroll
            for (int s = 0; s < 4; ++s) acc[rp][s] = make_float2(bv[s], bv[s]);

        if (t > 0) gemm_acc4(acc, sWh, sH, 64, rloc, gofs);
        gemm_acc4(acc, sWx, sXcur, FEAT, rloc, gofs);

        __syncthreads();  // GEMM reads of sH/sXcur complete

        if (t < TT - 1) storex(sXnxt);

        // cell update (all gate types local): s0=i, s1=f, s2=g, s3=o
        float2 hv[4];
        #pragma unroll
        for (int rp = 0; rp < 4; ++rp) {
            float2 iv = acc[rp][0], fv = acc[rp][1];
            float2 gv = acc[rp][2], ov = acc[rp][3];
            float2 cv = creg[rp];
            cv.x = sigf(fv.x) * cv.x + sigf(iv.x) * tanhfast(gv.x);
            cv.y = sigf(fv.y) * cv.y + sigf(iv.y) * tanhfast(gv.y);
            hv[rp].x = sigf(ov.x) * tanhfast(cv.x);
            hv[rp].y = sigf(ov.y) * tanhfast(cv.y);
            creg[rp] = cv;
        }
        *(float4*)&sH[j * PITCH + rloc]     = make_float4(hv[0].x, hv[0].y, hv[1].x, hv[1].y);
        *(float4*)&sH[j * PITCH + rloc + 4] = make_float4(hv[2].x, hv[2].y, hv[3].x, hv[3].y);

        if (LAYER == 0) {
            #pragma unroll
            for (int rp = 0; rp < 4; ++rp) {
                int r = rowbase + rloc + rp * 2;
                g_hs0[((size_t)r * TT + t) * HH + j] = hv[rp].x;
                g_hs0[((size_t)(r + 1) * TT + t) * HH + j] = hv[rp].y;
            }
        } else if (t == TT - 1) {
            #pragma unroll
            for (int rp = 0; rp < 4; ++rp) {
                int r = rowbase + rloc + rp * 2;
                g_hlast[r * HH + j] = hv[rp].x;
                g_hlast[(r + 1) * HH + j] = hv[rp].y;
            }
        }
        __syncthreads();  // sH(t) + sXnxt ready for next step
        const float* tmp = sXcur;
        sXcur = sXnxt;
        sXnxt = (float*)tmp;
    }
}

// =======================================================================
// GAT prep
// =======================================================================
__global__ void prep1(const float* __restrict__ Wt, const float* __restrict__ bt,
                      const float* __restrict__ a) {
    int tid = threadIdx.x;
    if (tid < 64) {
        float v = 0.f;
        for (int g = 0; g < 64; ++g) v += Wt[g * 64 + tid] * a[g];
        g_v1[tid] = v;
    } else if (tid < 128) {
        int k = tid - 64;
        float v = 0.f;
        for (int g = 0; g < 64; ++g) v += Wt[g * 64 + k] * a[64 + g];
        g_v2[k] = v;
    }
    if (tid == 0) {
        float c = 0.f;
        for (int g = 0; g < 64; ++g) c += bt[g] * a[g];
        g_c12[0] = c;
    }
    if (tid == 1) {
        float c = 0.f;
        for (int g = 0; g < 64; ++g) c += bt[g] * a[64 + g];
        g_c12[1] = c;
    }
}

__global__ void prep2() {
    int lane = threadIdx.x & 31, w = threadIdx.x >> 5;
    int r = blockIdx.x * 8 + w;
    float l0 = g_hlast[r * 64 + lane], l1 = g_hlast[r * 64 + 32 + lane];
    float p1 = l0 * g_v1[lane] + l1 * g_v1[lane + 32];
    float p2 = l0 * g_v2[lane] + l1 * g_v2[lane + 32];
    #pragma unroll
    for (int o = 16; o; o >>= 1) {
        p1 += __shfl_xor_sync(0xffffffffu, p1, o);
        p2 += __shfl_xor_sync(0xffffffffu, p2, o);
    }
    if (lane == 0) {
        g_s1[r] = p1 + g_c12[0];
        g_s2[r] = p2 + g_c12[1];
    }
}

// single-block bitonic sort of (s1, idx), ascending
__global__ void __launch_bounds__(1024, 1) sort_kernel() {
    extern __shared__ char sraw[];
    float* k = (float*)sraw;
    int* v = (int*)(sraw + NROWS * 4);
    int tid = threadIdx.x;
    for (int i = tid; i < NROWS; i += 1024) {
        k[i] = g_s1[i];
        v[i] = i;
    }
    for (int size = 2; size <= NROWS; size <<= 1) {
        for (int stride = size >> 1; stride > 0; stride >>= 1) {
            __syncthreads();
            #pragma unroll
            for (int e = 0; e < NROWS / 1024; ++e) {
                int i = e * 1024 + tid;
                int j = i ^ stride;
                if (j > i) {
                    bool up = ((i & size) == 0);
                    float ki = k[i], kj = k[j];
                    if ((ki > kj) == up) {
                        k[i] = kj; k[j] = ki;
                        int t = v[i]; v[i] = v[j]; v[j] = t;
                    }
                }
            }
        }
    }
    __syncthreads();
    for (int i = tid; i < NROWS; i += 1024) {
        g_s1sorted[i] = k[i];
        g_sidx[i] = v[i];
    }
}

// per-chunk sums of A_j*[x_j,1] and B_j*[x_j,1]  (65 dims; dim 64 = denominator)
__global__ void scan1() {
    __shared__ float sA[64], sB[64];
    __shared__ int sI[64];
    int c = blockIdx.x, tid = threadIdx.x;
    if (tid < 64) {
        float smax = g_s1sorted[NROWS - 1];
        float key = g_s1sorted[c * 64 + tid];
        float A = __expf(key - smax);
        float B = __expf(0.01f * (key - smax));
        sA[tid] = A; sB[tid] = B;
        sI[tid] = g_sidx[c * 64 + tid];
        g_A[c * 64 + tid] = A;
        g_B[c * 64 + tid] = B;
    }
    __syncthreads();
    if (tid <= 64) {
        float sa = 0.f, sb = 0.f;
        #pragma unroll 4
        for (int m = 0; m < 64; ++m) {
            float xv = (tid < 64) ? g_hlast[sI[m] * 64 + tid] : 1.f;
            sa += sA[m] * xv;
            sb += sB[m] * xv;
        }
        g_chunkA[c * 65 + tid] = sa;
        g_chunkB[c * 65 + tid] = sb;
    }
}

// parallel exclusive scans of chunk sums: B forward, A reverse.
// one block per dim d (65 blocks), 128 threads (one per chunk).
__global__ void scan2() {
    __shared__ float bufB[NCHUNK], bufA[NCHUNK];
    int d = blockIdx.x;
    int c = threadIdx.x;
    float origB = g_chunkB[c * 65 + d];
    float origA = g_chunkA[c * 65 + d];
    bufB[c] = origB;
    bufA[NCHUNK - 1 - c] = origA;   // reversed for suffix scan
    __syncthreads();
    #pragma unroll
    for (int off = 1; off < NCHUNK; off <<= 1) {
        float tb = (c >= off) ? bufB[c - off] : 0.f;
        float ta = (c >= off) ? bufA[c - off] : 0.f;
        __syncthreads();
        bufB[c] += tb;
        bufA[c] += ta;
        __syncthreads();
    }
    // exclusive values
    g_chunkB[c * 65 + d] = bufB[c] - origB;
    g_chunkA[c * 65 + d] = bufA[NCHUNK - 1 - c] - origA;
}

// full prefix/suffix arrays
__global__ void scan3() {
    __shared__ float sA[64], sB[64];
    __shared__ int sI[64];
    int c = blockIdx.x, tid = threadIdx.x;
    if (tid < 64) {
        sA[tid] = g_A[c * 64 + tid];
        sB[tid] = g_B[c * 64 + tid];
        sI[tid] = g_sidx[c * 64 + tid];
    }
    __syncthreads();
    if (tid <= 64) {
        int d = tid;
        float run = g_chunkB[c * 65 + d];
        #pragma unroll 4
        for (int m = 0; m < 64; ++m) {
            size_t kk = (size_t)(c * 64 + m);
            g_preB[kk * 65 + d] = run;
            float xv = (d < 64) ? g_hlast[sI[m] * 64 + d] : 1.f;
            run += sB[m] * xv;
        }
        if (c == NCHUNK - 1) g_preB[(size_t)NROWS * 65 + d] = run;
        float runA = g_chunkA[c * 65 + d];
        #pragma unroll 4
        for (int m = 63; m >= 0; --m) {
            float xv = (d < 64) ? g_hlast[sI[m] * 64 + d] : 1.f;
            runA += sA[m] * xv;
            g_suffA[(size_t)(c * 64 + m) * 65 + d] = runA;
        }
        if (c == NCHUNK - 1) g_suffA[(size_t)NROWS * 65 + d] = 0.f;
    }
}

// =======================================================================
// Final: per row i — binary search kink, combine prefix/suffix, residual,
// FC + lrelu + output dot. One warp per row, 8 warps / block.
// =======================================================================
__global__ void __launch_bounds__(256)
final_kernel(const float* __restrict__ Wfc, const float* __restrict__ bfc,
             const float* __restrict__ Wout, const float* __restrict__ bout,
             float* __restrict__ out) {
    __shared__ float sWfcT[64 * 65];  // [k][c]
    __shared__ float sWo[64], sBfc[64];
    __shared__ float sZ[8][64];
    int tid = threadIdx.x;
    for (int idx = tid; idx < 4096; idx += 256) {
        int cc = idx >> 6, kq = idx & 63;
        sWfcT[kq * 65 + cc] = Wfc[idx];
    }
    if (tid < 64) {
        sWo[tid] = Wout[tid];
        sBfc[tid] = bfc[tid];
    }
    __syncthreads();

    int wy = tid >> 5, l = tid & 31;
    int i = blockIdx.x * 8 + wy;
    float smax = g_s1sorted[NROWS - 1];
    float s2 = g_s2[i];
    float thr = -s2;

    int kk = 0;
    #pragma unroll
    for (int st = 4096; st > 0; st >>= 1)
        if (kk + st <= NROWS && g_s1sorted[kk + st - 1] <= thr) kk += st;

    float u = s2 + smax;
    float fA, fB;
    if (u > 0.f) { fA = 1.f;               fB = __expf(-0.99f * u); }
    else         { fA = __expf(0.99f * u); fB = 1.f; }

    const float* suff = &g_suffA[(size_t)kk * 65];
    const float* pre  = &g_preB[(size_t)kk * 65];
    float denom = fA * suff[64] + fB * pre[64];
    float inv = __fdividef(1.f, denom);
    #pragma unroll
    for (int h = 0; h < 2; ++h) {
        int d = l + h * 32;
        float num = fA * suff[d] + fB * pre[d];
        sZ[wy][d] = num * inv + g_hlast[i * 64 + d];
    }
    __syncwarp();

    float yp = 0.f;
    #pragma unroll
    for (int h = 0; h < 2; ++h) {
        int c = l + h * 32;
        float dot = sBfc[c];
        #pragma unroll 16
        for (int kq = 0; kq < 64; ++kq) dot += sZ[wy][kq] * sWfcT[kq * 65 + c];
        dot = dot > 0.f ? dot : 0.01f * dot;
        yp += dot * sWo[c];
    }
    #pragma unroll
    for (int o = 16; o; o >>= 1) yp += __shfl_xor_sync(0xffffffffu, yp, o);
    if (l == 0) out[i] = yp + bout[0];
}

// =======================================================================
extern "C" void kernel_launch(void* const* d_in, const int* in_sizes, int n_in,
                              void* d_out, int out_size) {
    const float* x    = (const float*)d_in[0];
    const float* Wih0 = (const float*)d_in[1];
    const float* Whh0 = (const float*)d_in[2];
    const float* bih0 = (const float*)d_in[3];
    const float* bhh0 = (const float*)d_in[4];
    const float* Wih1 = (const float*)d_in[5];
    const float* Whh1 = (const float*)d_in[6];
    const float* bih1 = (const float*)d_in[7];
    const float* bhh1 = (const float*)d_in[8];
    const float* Wt   = (const float*)d_in[9];
    const float* bt   = (const float*)d_in[10];
    const float* a    = (const float*)d_in[11];
    const float* Wfc  = (const float*)d_in[12];
    const float* bfc  = (const float*)d_in[13];
    const float* Wout = (const float*)d_in[14];
    const float* bout = (const float*)d_in[15];
    float* out = (float*)d_out;

    const int SM_L0 = (64 * 256 + 6 * 256 + 256 + 64 * PITCH + 2 * 6 * PITCH) * 4;
    const int SM_L1 = (64 * 256 + 64 * 256 + 256 + 64 * PITCH + 2 * 64 * PITCH) * 4;
    const int SM_SORT = NROWS * 8;

    cudaFuncSetAttribute(lstm_kernel<6, 0>, cudaFuncAttributeMaxDynamicSharedMemorySize, SM_L0);
    cudaFuncSetAttribute(lstm_kernel<64, 1>, cudaFuncAttributeMaxDynamicSharedMemorySize, SM_L1);
    cudaFuncSetAttribute(sort_kernel, cudaFuncAttributeMaxDynamicSharedMemorySize, SM_SORT);

    lstm_kernel<6, 0><<<NROWS / 64, 512, SM_L0>>>(x, Wih0, Whh0, bih0, bhh0);
    lstm_kernel<64, 1><<<NROWS / 64, 512, SM_L1>>>(x, Wih1, Whh1, bih1, bhh1);
    prep1<<<1, 128>>>(Wt, bt, a);
    prep2<<<NROWS / 8, 256>>>();
    sort_kernel<<<1, 1024, SM_SORT>>>();
    scan1<<<NCHUNK, 128>>>();
    scan2<<<65, NCHUNK>>>();
    scan3<<<NCHUNK, 128>>>();
    final_kernel<<<NROWS / 8, 256>>>(Wfc, bfc, Wout, bout, out);
}

// round 6
// speedup vs baseline: 2.3013x; 1.7329x over previous
#include <cuda_runtime.h>
#include <cuda_bf16.h>
#include <math.h>
#include <stdint.h>

#define NROWS 8192
#define TT    60
#define NCHUNK 128

// -------- device scratch --------
__device__ uint32_t g_hs0[(size_t)TT * NROWS * 64];  // L0 h, packed bf16 (hi | lo<<16)
__device__ float g_hlast[NROWS * 64];
__device__ float g_s1[NROWS];
__device__ float g_s2[NROWS];
__device__ float g_v1[64];
__device__ float g_v2[64];
__device__ float g_c12[2];
__device__ float g_s1sorted[NROWS];
__device__ int   g_sidx[NROWS];
__device__ float g_A[NROWS];
__device__ float g_B[NROWS];
__device__ float g_chunkA[NCHUNK * 65];
__device__ float g_chunkB[NCHUNK * 65];
__device__ float g_preB[(size_t)(NROWS + 1) * 65];
__device__ float g_suffA[(size_t)(NROWS + 1) * 65];

__device__ __forceinline__ float sigf(float x) { return __fdividef(1.f, 1.f + __expf(-x)); }
__device__ __forceinline__ float tanhfast(float x) { return 1.f - __fdividef(2.f, __expf(2.f * x) + 1.f); }

// -------- warp-MMA helpers (baseline sm_80+ ISA; no tcgen05) --------
__device__ __forceinline__ uint32_t smem_u32(const void* p) {
    uint32_t a;
    asm("{ .reg .u64 t; cvta.to.shared.u64 t, %1; cvt.u32.u64 %0, t; }" : "=r"(a) : "l"(p));
    return a;
}
__device__ __forceinline__ void ldsm4(uint32_t* r, uint32_t a) {
    asm volatile("ldmatrix.sync.aligned.m8n8.x4.shared.b16 {%0,%1,%2,%3}, [%4];"
                 : "=r"(r[0]), "=r"(r[1]), "=r"(r[2]), "=r"(r[3]) : "r"(a));
}
__device__ __forceinline__ void ldsm4t(uint32_t* r, uint32_t a) {
    asm volatile("ldmatrix.sync.aligned.m8n8.x4.trans.shared.b16 {%0,%1,%2,%3}, [%4];"
                 : "=r"(r[0]), "=r"(r[1]), "=r"(r[2]), "=r"(r[3]) : "r"(a));
}
__device__ __forceinline__ void mma16816(float* d, const uint32_t* a, const uint32_t* b) {
    asm volatile(
        "mma.sync.aligned.m16n8k16.row.col.f32.bf16.bf16.f32 "
        "{%0,%1,%2,%3}, {%4,%5,%6,%7}, {%8,%9}, {%0,%1,%2,%3};"
        : "+f"(d[0]), "+f"(d[1]), "+f"(d[2]), "+f"(d[3])
        : "r"(a[0]), "r"(a[1]), "r"(a[2]), "r"(a[3]), "r"(b[0]), "r"(b[1]));
}
__device__ __forceinline__ uint32_t prmt(uint32_t a, uint32_t b, uint32_t s) {
    uint32_t r;
    asm("prmt.b32 %0, %1, %2, %3;" : "=r"(r) : "r"(a), "r"(b), "r"(s));
    return r;
}
__device__ __forceinline__ void bfsplit(float v, uint32_t& hi, uint32_t& lo) {
    __nv_bfloat16 h = __float2bfloat16(v);
    __nv_bfloat16 l = __float2bfloat16(v - __bfloat162float(h));
    hi = *(uint16_t*)&h;
    lo = *(uint16_t*)&l;
}
// A tile [64 rows][128 k] bf16, 256B/row, swizzled 16B chunks
__device__ __forceinline__ uint32_t offA(int r, int k) {
    int ck = k >> 3;
    return (uint32_t)(r * 256 + (((ck & 8) | ((ck ^ r) & 7)) << 4) + (k & 7) * 2);
}
// W tile [k][256 n] bf16, 512B/row
__device__ __forceinline__ uint32_t offW(int k, int n) {
    int cn = n >> 3;
    return (uint32_t)(k * 512 + (((cn & 24) | ((cn ^ k) & 7)) << 4) + (n & 7) * 2);
}

// =======================================================================
// HMMA LSTM: 128 blocks x 64 rows, 512 threads (16 warps).
// G[64,256] = [h|x] @ W^T, cols permuted n=4j+type. Warp (rw=wid&3 rows,
// cg=wid>>2 cols). 3-MMA bf16 split. Cell update register-local after
// one xor-1 shuffle; h repacked to SMEM via xor-2 shuffle.
// =======================================================================
template <int KW, int NCH, int FEAT, int LAYER>
__global__ void __launch_bounds__(512, 1)
lstm_mma(const float* __restrict__ xin, const float* __restrict__ Wih,
         const float* __restrict__ Whh, const float* __restrict__ bih,
         const float* __restrict__ bhh) {
    extern __shared__ char smem[];
    const int W_HI = 0, W_LO = KW * 512;
    const int A_HI = 2 * KW * 512, A_LO = A_HI + 16384;
    const int S_BIAS = A_LO + 16384;
    const uint32_t sbase = smem_u32(smem);

    const int tid = threadIdx.x, lane = tid & 31, wid = tid >> 5;
    const int rw = wid & 3, cg = wid >> 2;
    const int t4 = lane & 3, g8 = lane >> 2;
    const int r0 = rw * 16;
    const int rowb = blockIdx.x * 64;
    const int row_st = r0 + g8 + ((t4 & 1) ? 8 : 0);
    const int m = lane >> 3, q = lane & 7;

    // ---- stage W (permuted, split hi/lo) ----
    for (int idx = tid; idx < KW * 256; idx += 512) {
        int k = idx >> 8, n = idx & 255;
        int go = (n & 3) * 64 + (n >> 2);
        float w = (k < 64) ? Whh[go * 64 + k]
                           : ((k - 64 < FEAT) ? Wih[go * FEAT + (k - 64)] : 0.f);
        uint32_t hi, lo;
        bfsplit(w, hi, lo);
        uint32_t o = offW(k, n);
        *(uint16_t*)(smem + W_HI + o) = (uint16_t)hi;
        *(uint16_t*)(smem + W_LO + o) = (uint16_t)lo;
    }
    // zero both A planes (32KB)
    for (int i = tid; i < 2048; i += 512) ((uint4*)(smem + A_HI))[i] = make_uint4(0, 0, 0, 0);
    if (tid < 256) {
        int go = (tid & 3) * 64 + (tid >> 2);
        ((float*)(smem + S_BIAS))[tid] = bih[go] + bhh[go];
    }
    __syncthreads();

    // per-thread x staging constants
    int xrow = 0, xd = 0;
    if (LAYER == 0) { xrow = tid / 6; xd = tid - xrow * 6; }
    float xf = 0.f;
    uint32_t xw[8];

    auto pfx = [&](int t) {
        if (LAYER == 0) {
            if (tid < 384) xf = xin[((size_t)(rowb + xrow) * TT + t) * 6 + xd];
        } else {
            const uint32_t* p = g_hs0 + ((size_t)t * NROWS + rowb + (tid >> 3)) * 64 + (tid & 7) * 8;
            *(uint4*)&xw[0] = *(const uint4*)p;
            *(uint4*)&xw[4] = *(const uint4*)(p + 4);
        }
    };
    auto stx = [&]() {
        if (LAYER == 0) {
            if (tid < 384) {
                uint32_t hi, lo;
                bfsplit(xf, hi, lo);
                uint32_t o = offA(xrow, 64 + xd);
                *(uint16_t*)(smem + A_HI + o) = (uint16_t)hi;
                *(uint16_t*)(smem + A_LO + o) = (uint16_t)lo;
            }
        } else {
            int r = tid >> 3, kb = 64 + (tid & 7) * 8;
            uint32_t o = offA(r, kb);
            *(uint4*)(smem + A_HI + o) =
                make_uint4(prmt(xw[0], xw[1], 0x5410), prmt(xw[2], xw[3], 0x5410),
                           prmt(xw[4], xw[5], 0x5410), prmt(xw[6], xw[7], 0x5410));
            *(uint4*)(smem + A_LO + o) =
                make_uint4(prmt(xw[0], xw[1], 0x7632), prmt(xw[2], xw[3], 0x7632),
                           prmt(xw[4], xw[5], 0x7632), prmt(xw[6], xw[7], 0x7632));
        }
    };

    pfx(0);
    stx();
    __syncthreads();

    float c[8];
    #pragma unroll
    for (int nt = 0; nt < 8; ++nt) c[nt] = 0.f;

    #pragma unroll 1
    for (int t = 0; t < TT; ++t) {
        // init accumulators from bias
        float d[8][4];
        #pragma unroll
        for (int nt = 0; nt < 8; ++nt) {
            float2 b2 = *(const float2*)(smem + S_BIAS + (cg * 64 + nt * 8 + t4 * 2) * 4);
            d[nt][0] = b2.x; d[nt][1] = b2.y; d[nt][2] = b2.x; d[nt][3] = b2.y;
        }
        if (t < TT - 1) pfx(t + 1);  // LDG overlapped with MMA

        // ---- MMA phase ----
        #pragma unroll
        for (int ch = 0; ch < NCH; ++ch) {
            int ar = r0 + (m & 1) * 8 + q;
            int ak = ch * 16 + (m >> 1) * 8;
            uint32_t ao = offA(ar, ak);
            uint32_t ahi[4], alo[4];
            ldsm4(ahi, sbase + A_HI + ao);
            ldsm4(alo, sbase + A_LO + ao);
            int bk = ch * 16 + (m & 1) * 8 + q;
            uint32_t bhi[16], blo[16];
            #pragma unroll
            for (int p = 0; p < 4; ++p) {
                uint32_t bo = offW(bk, cg * 64 + (2 * p + (m >> 1)) * 8);
                ldsm4t(&bhi[4 * p], sbase + W_HI + bo);
                ldsm4t(&blo[4 * p], sbase + W_LO + bo);
            }
            #pragma unroll
            for (int nt = 0; nt < 8; ++nt) mma16816(d[nt], ahi, &bhi[2 * nt]);
            #pragma unroll
            for (int nt = 0; nt < 8; ++nt) mma16816(d[nt], alo, &bhi[2 * nt]);
            #pragma unroll
            for (int nt = 0; nt < 8; ++nt) mma16816(d[nt], ahi, &blo[2 * nt]);
        }
        __syncthreads();  // all reads of A done before rewrite

        // ---- cell phase ----
        float hf[8];
        uint32_t w0a[8], w1a[8];
        #pragma unroll
        for (int nt = 0; nt < 8; ++nt) {
            float e0 = __shfl_xor_sync(0xffffffffu, d[nt][0], 1);
            float e1 = __shfl_xor_sync(0xffffffffu, d[nt][1], 1);
            float e2 = __shfl_xor_sync(0xffffffffu, d[nt][2], 1);
            float e3 = __shfl_xor_sync(0xffffffffu, d[nt][3], 1);
            float iv, fv, gv, ov;
            if (t4 & 1) { iv = e2; fv = e3; gv = d[nt][2]; ov = d[nt][3]; }
            else        { iv = d[nt][0]; fv = d[nt][1]; gv = e0; ov = e1; }
            float cc = sigf(fv) * c[nt] + sigf(iv) * tanhfast(gv);
            c[nt] = cc;
            float hh = sigf(ov) * tanhfast(cc);
            hf[nt] = hh;
            uint32_t hi, lo;
            bfsplit(hh, hi, lo);
            uint32_t hpk = hi | (lo << 16);
            uint32_t rv = __shfl_xor_sync(0xffffffffu, hpk, 2);
            w0a[nt] = (t4 & 2) ? rv : hpk;   // j even
            w1a[nt] = (t4 & 2) ? hpk : rv;   // j odd
        }
        const int ntb = (t4 & 2) ? 4 : 0;
        const int kb = cg * 16 + ntb * 2;
        if (t < TT - 1) {
            // h -> A (k 0..63), hi/lo planes
            uint32_t o = offA(row_st, kb);
            *(uint2*)(smem + A_HI + o) =
                make_uint2(prmt(w0a[ntb], w1a[ntb], 0x5410), prmt(w0a[ntb + 1], w1a[ntb + 1], 0x5410));
            *(uint2*)(smem + A_HI + o + 8) =
                make_uint2(prmt(w0a[ntb + 2], w1a[ntb + 2], 0x5410), prmt(w0a[ntb + 3], w1a[ntb + 3], 0x5410));
            *(uint2*)(smem + A_LO + o) =
                make_uint2(prmt(w0a[ntb], w1a[ntb], 0x7632), prmt(w0a[ntb + 1], w1a[ntb + 1], 0x7632));
            *(uint2*)(smem + A_LO + o + 8) =
                make_uint2(prmt(w0a[ntb + 2], w1a[ntb + 2], 0x7632), prmt(w0a[ntb + 3], w1a[ntb + 3], 0x7632));
            stx();  // x(t+1)
        }
        if (LAYER == 0) {
            uint32_t* dst = g_hs0 + ((size_t)t * NROWS + rowb + row_st) * 64 + kb;
            *(uint4*)dst = make_uint4(w0a[ntb], w1a[ntb], w0a[ntb + 1], w1a[ntb + 1]);
            *(uint4*)(dst + 4) = make_uint4(w0a[ntb + 2], w1a[ntb + 2], w0a[ntb + 3], w1a[ntb + 3]);
        } else if (t == TT - 1) {
            #pragma unroll
            for (int nt = 0; nt < 8; ++nt)
                g_hlast[(rowb + row_st) * 64 + cg * 16 + 2 * nt + (t4 >> 1)] = hf[nt];
        }
        __syncthreads();  // writes visible before next MMA phase
    }
}

// =======================================================================
// GAT prep + O(N) attention + head (R3-passing versions, unchanged)
// =======================================================================
__global__ void prep1(const float* __restrict__ Wt, const float* __restrict__ bt,
                      const float* __restrict__ a) {
    int tid = threadIdx.x;
    if (tid < 64) {
        float v = 0.f;
        for (int g = 0; g < 64; ++g) v += Wt[g * 64 + tid] * a[g];
        g_v1[tid] = v;
    } else if (tid < 128) {
        int k = tid - 64;
        float v = 0.f;
        for (int g = 0; g < 64; ++g) v += Wt[g * 64 + k] * a[64 + g];
        g_v2[k] = v;
    }
    if (tid == 0) {
        float c = 0.f;
        for (int g = 0; g < 64; ++g) c += bt[g] * a[g];
        g_c12[0] = c;
    }
    if (tid == 1) {
        float c = 0.f;
        for (int g = 0; g < 64; ++g) c += bt[g] * a[64 + g];
        g_c12[1] = c;
    }
}

__global__ void prep2() {
    int lane = threadIdx.x & 31, w = threadIdx.x >> 5;
    int r = blockIdx.x * 8 + w;
    float l0 = g_hlast[r * 64 + lane], l1 = g_hlast[r * 64 + 32 + lane];
    float p1 = l0 * g_v1[lane] + l1 * g_v1[lane + 32];
    float p2 = l0 * g_v2[lane] + l1 * g_v2[lane + 32];
    #pragma unroll
    for (int o = 16; o; o >>= 1) {
        p1 += __shfl_xor_sync(0xffffffffu, p1, o);
        p2 += __shfl_xor_sync(0xffffffffu, p2, o);
    }
    if (lane == 0) {
        g_s1[r] = p1 + g_c12[0];
        g_s2[r] = p2 + g_c12[1];
    }
}

__global__ void __launch_bounds__(1024, 1) sort_kernel() {
    extern __shared__ char sraw[];
    float* k = (float*)sraw;
    int* v = (int*)(sraw + NROWS * 4);
    int tid = threadIdx.x;
    for (int i = tid; i < NROWS; i += 1024) { k[i] = g_s1[i]; v[i] = i; }
    for (int size = 2; size <= NROWS; size <<= 1) {
        for (int stride = size >> 1; stride > 0; stride >>= 1) {
            __syncthreads();
            #pragma unroll
            for (int e = 0; e < NROWS / 1024; ++e) {
                int i = e * 1024 + tid;
                int j = i ^ stride;
                if (j > i) {
                    bool up = ((i & size) == 0);
                    float ki = k[i], kj = k[j];
                    if ((ki > kj) == up) {
                        k[i] = kj; k[j] = ki;
                        int t = v[i]; v[i] = v[j]; v[j] = t;
                    }
                }
            }
        }
    }
    __syncthreads();
    for (int i = tid; i < NROWS; i += 1024) { g_s1sorted[i] = k[i]; g_sidx[i] = v[i]; }
}

__global__ void scan1() {
    __shared__ float sA[64], sB[64];
    __shared__ int sI[64];
    int c = blockIdx.x, tid = threadIdx.x;
    if (tid < 64) {
        float smax = g_s1sorted[NROWS - 1];
        float key = g_s1sorted[c * 64 + tid];
        float A = __expf(key - smax);
        float B = __expf(0.01f * (key - smax));
        sA[tid] = A; sB[tid] = B;
        sI[tid] = g_sidx[c * 64 + tid];
        g_A[c * 64 + tid] = A;
        g_B[c * 64 + tid] = B;
    }
    __syncthreads();
    if (tid <= 64) {
        float sa = 0.f, sb = 0.f;
        #pragma unroll 4
        for (int mq = 0; mq < 64; ++mq) {
            float xv = (tid < 64) ? g_hlast[sI[mq] * 64 + tid] : 1.f;
            sa += sA[mq] * xv;
            sb += sB[mq] * xv;
        }
        g_chunkA[c * 65 + tid] = sa;
        g_chunkB[c * 65 + tid] = sb;
    }
}

__global__ void scan2() {
    __shared__ float bufB[NCHUNK], bufA[NCHUNK];
    int d = blockIdx.x;
    int c = threadIdx.x;
    float origB = g_chunkB[c * 65 + d];
    float origA = g_chunkA[c * 65 + d];
    bufB[c] = origB;
    bufA[NCHUNK - 1 - c] = origA;
    __syncthreads();
    #pragma unroll
    for (int off = 1; off < NCHUNK; off <<= 1) {
        float tb = (c >= off) ? bufB[c - off] : 0.f;
        float ta = (c >= off) ? bufA[c - off] : 0.f;
        __syncthreads();
        bufB[c] += tb;
        bufA[c] += ta;
        __syncthreads();
    }
    g_chunkB[c * 65 + d] = bufB[c] - origB;
    g_chunkA[c * 65 + d] = bufA[NCHUNK - 1 - c] - origA;
}

__global__ void scan3() {
    __shared__ float sA[64], sB[64];
    __shared__ int sI[64];
    int c = blockIdx.x, tid = threadIdx.x;
    if (tid < 64) {
        sA[tid] = g_A[c * 64 + tid];
        sB[tid] = g_B[c * 64 + tid];
        sI[tid] = g_sidx[c * 64 + tid];
    }
    __syncthreads();
    if (tid <= 64) {
        int d = tid;
        float run = g_chunkB[c * 65 + d];
        #pragma unroll 4
        for (int mq = 0; mq < 64; ++mq) {
            size_t kk = (size_t)(c * 64 + mq);
            g_preB[kk * 65 + d] = run;
            float xv = (d < 64) ? g_hlast[sI[mq] * 64 + d] : 1.f;
            run += sB[mq] * xv;
        }
        if (c == NCHUNK - 1) g_preB[(size_t)NROWS * 65 + d] = run;
        float runA = g_chunkA[c * 65 + d];
        #pragma unroll 4
        for (int mq = 63; mq >= 0; --mq) {
            float xv = (d < 64) ? g_hlast[sI[mq] * 64 + d] : 1.f;
            runA += sA[mq] * xv;
            g_suffA[(size_t)(c * 64 + mq) * 65 + d] = runA;
        }
        if (c == NCHUNK - 1) g_suffA[(size_t)NROWS * 65 + d] = 0.f;
    }
}

__global__ void __launch_bounds__(256)
final_kernel(const float* __restrict__ Wfc, const float* __restrict__ bfc,
             const float* __restrict__ Wout, const float* __restrict__ bout,
             float* __restrict__ out) {
    __shared__ float sWfcT[64 * 65];
    __shared__ float sWo[64], sBfc[64];
    __shared__ float sZ[8][64];
    int tid = threadIdx.x;
    for (int idx = tid; idx < 4096; idx += 256) {
        int cc = idx >> 6, kq = idx & 63;
        sWfcT[kq * 65 + cc] = Wfc[idx];
    }
    if (tid < 64) { sWo[tid] = Wout[tid]; sBfc[tid] = bfc[tid]; }
    __syncthreads();

    int wy = tid >> 5, l = tid & 31;
    int i = blockIdx.x * 8 + wy;
    float smax = g_s1sorted[NROWS - 1];
    float s2 = g_s2[i];
    float thr = -s2;

    int kk = 0;
    #pragma unroll
    for (int st = 4096; st > 0; st >>= 1)
        if (kk + st <= NROWS && g_s1sorted[kk + st - 1] <= thr) kk += st;

    float u = s2 + smax;
    float fA, fB;
    if (u > 0.f) { fA = 1.f;               fB = __expf(-0.99f * u); }
    else         { fA = __expf(0.99f * u); fB = 1.f; }

    const float* suff = &g_suffA[(size_t)kk * 65];
    const float* pre  = &g_preB[(size_t)kk * 65];
    float inv = __fdividef(1.f, fA * suff[64] + fB * pre[64]);
    #pragma unroll
    for (int h = 0; h < 2; ++h) {
        int d = l + h * 32;
        sZ[wy][d] = (fA * suff[d] + fB * pre[d]) * inv + g_hlast[i * 64 + d];
    }
    __syncwarp();

    float yp = 0.f;
    #pragma unroll
    for (int h = 0; h < 2; ++h) {
        int c = l + h * 32;
        float dot = sBfc[c];
        #pragma unroll 16
        for (int kq = 0; kq < 64; ++kq) dot += sZ[wy][kq] * sWfcT[kq * 65 + c];
        dot = dot > 0.f ? dot : 0.01f * dot;
        yp += dot * sWo[c];
    }
    #pragma unroll
    for (int o = 16; o; o >>= 1) yp += __shfl_xor_sync(0xffffffffu, yp, o);
    if (l == 0) out[i] = yp + bout[0];
}

// =======================================================================
extern "C" void kernel_launch(void* const* d_in, const int* in_sizes, int n_in,
                              void* d_out, int out_size) {
    const float* x    = (const float*)d_in[0];
    const float* Wih0 = (const float*)d_in[1];
    const float* Whh0 = (const float*)d_in[2];
    const float* bih0 = (const float*)d_in[3];
    const float* bhh0 = (const float*)d_in[4];
    const float* Wih1 = (const float*)d_in[5];
    const float* Whh1 = (const float*)d_in[6];
    const float* bih1 = (const float*)d_in[7];
    const float* bhh1 = (const float*)d_in[8];
    const float* Wt   = (const float*)d_in[9];
    const float* bt   = (const float*)d_in[10];
    const float* a    = (const float*)d_in[11];
    const float* Wfc  = (const float*)d_in[12];
    const float* bfc  = (const float*)d_in[13];
    const float* Wout = (const float*)d_in[14];
    const float* bout = (const float*)d_in[15];
    float* out = (float*)d_out;

    const int SM_L0 = 80 * 1024 + 33792;    // 115712 B
    const int SM_L1 = 128 * 1024 + 33792;   // 164864 B
    const int SM_SORT = NROWS * 8;

    cudaFuncSetAttribute(lstm_mma<80, 5, 6, 0>, cudaFuncAttributeMaxDynamicSharedMemorySize, SM_L0);
    cudaFuncSetAttribute(lstm_mma<128, 8, 64, 1>, cudaFuncAttributeMaxDynamicSharedMemorySize, SM_L1);
    cudaFuncSetAttribute(sort_kernel, cudaFuncAttributeMaxDynamicSharedMemorySize, SM_SORT);

    lstm_mma<80, 5, 6, 0><<<NROWS / 64, 512, SM_L0>>>(x, Wih0, Whh0, bih0, bhh0);
    lstm_mma<128, 8, 64, 1><<<NROWS / 64, 512, SM_L1>>>(x, Wih1, Whh1, bih1, bhh1);
    prep1<<<1, 128>>>(Wt, bt, a);
    prep2<<<NROWS / 8, 256>>>();
    sort_kernel<<<1, 1024, SM_SORT>>>();
    scan1<<<NCHUNK, 128>>>();
    scan2<<<65, NCHUNK>>>();
    scan3<<<NCHUNK, 128>>>();
    final_kernel<<<NROWS / 8, 256>>>(Wfc, bfc, Wout, bout, out);
}

// round 7
// speedup vs baseline: 2.7139x; 1.1793x over previous
#include <cuda_runtime.h>
#include <cuda_bf16.h>
#include <math.h>
#include <stdint.h>

#define NROWS 8192
#define TT    60
#define NCHUNK 128

// -------- device scratch --------
__device__ uint32_t g_hs0[(size_t)TT * NROWS * 64];  // L0 h, packed bf16 (hi | lo<<16)
__device__ float g_hlast[NROWS * 64];
__device__ float g_s1[NROWS];
__device__ float g_s2[NROWS];
__device__ float g_v1[64];
__device__ float g_v2[64];
__device__ float g_c12[2];
__device__ float g_s1sorted[NROWS];
__device__ int   g_sidx[NROWS];
__device__ float g_A[NROWS];
__device__ float g_B[NROWS];
__device__ float g_chunkA[NCHUNK * 65];
__device__ float g_chunkB[NCHUNK * 65];
__device__ float g_preB[(size_t)(NROWS + 1) * 65];
__device__ float g_suffA[(size_t)(NROWS + 1) * 65];

__device__ __forceinline__ float sigf(float x) { return __fdividef(1.f, 1.f + __expf(-x)); }
__device__ __forceinline__ float tanha(float x) {
    float r;
    asm("tanh.approx.f32 %0, %1;" : "=f"(r) : "f"(x));
    return r;
}
__device__ __forceinline__ float siga(float x) { return fmaf(tanha(0.5f * x), 0.5f, 0.5f); }

// -------- warp-MMA helpers (baseline sm_80+ ISA) --------
__device__ __forceinline__ uint32_t smem_u32(const void* p) {
    uint32_t a;
    asm("{ .reg .u64 t; cvta.to.shared.u64 t, %1; cvt.u32.u64 %0, t; }" : "=r"(a) : "l"(p));
    return a;
}
__device__ __forceinline__ void barg(int id) {
    asm volatile("bar.sync %0, 128;" :: "r"(id) : "memory");
}
__device__ __forceinline__ void ldsm4(uint32_t* r, uint32_t a) {
    asm volatile("ldmatrix.sync.aligned.m8n8.x4.shared.b16 {%0,%1,%2,%3}, [%4];"
                 : "=r"(r[0]), "=r"(r[1]), "=r"(r[2]), "=r"(r[3]) : "r"(a));
}
__device__ __forceinline__ void ldsm4t(uint32_t* r, uint32_t a) {
    asm volatile("ldmatrix.sync.aligned.m8n8.x4.trans.shared.b16 {%0,%1,%2,%3}, [%4];"
                 : "=r"(r[0]), "=r"(r[1]), "=r"(r[2]), "=r"(r[3]) : "r"(a));
}
__device__ __forceinline__ void mma16816(float* d, const uint32_t* a, const uint32_t* b) {
    asm volatile(
        "mma.sync.aligned.m16n8k16.row.col.f32.bf16.bf16.f32 "
        "{%0,%1,%2,%3}, {%4,%5,%6,%7}, {%8,%9}, {%0,%1,%2,%3};"
        : "+f"(d[0]), "+f"(d[1]), "+f"(d[2]), "+f"(d[3])
        : "r"(a[0]), "r"(a[1]), "r"(a[2]), "r"(a[3]), "r"(b[0]), "r"(b[1]));
}
__device__ __forceinline__ uint32_t prmt(uint32_t a, uint32_t b, uint32_t s) {
    uint32_t r;
    asm("prmt.b32 %0, %1, %2, %3;" : "=r"(r) : "r"(a), "r"(b), "r"(s));
    return r;
}
__device__ __forceinline__ void bfsplit(float v, uint32_t& hi, uint32_t& lo) {
    __nv_bfloat16 h = __float2bfloat16(v);
    __nv_bfloat16 l = __float2bfloat16(v - __bfloat162float(h));
    hi = *(uint16_t*)&h;
    lo = *(uint16_t*)&l;
}
// A tile [64 rows][128 k] bf16, 256B/row, swizzled 16B chunks
__device__ __forceinline__ uint32_t offA(int r, int k) {
    int ck = k >> 3;
    return (uint32_t)(r * 256 + (((ck & 8) | ((ck ^ r) & 7)) << 4) + (k & 7) * 2);
}
// W tile [k][256 n] bf16, 512B/row
__device__ __forceinline__ uint32_t offW(int k, int n) {
    int cn = n >> 3;
    return (uint32_t)(k * 512 + (((cn & 24) | ((cn ^ k) & 7)) << 4) + (n & 7) * 2);
}

// =======================================================================
// HMMA LSTM: 128 blocks x 64 rows, 512 threads (16 warps).
// Warp (rw=wid&3 rows, cg=wid>>2 cols). Row-group rw = 4 warps {cg=0..3}
// owns A rows rw*16..+15 exclusively -> per-step sync is bar.sync(rw+1,128),
// letting the 4 groups drift and overlap MMA/MUFU/LSU phases.
// 3-MMA bf16 split; cell update register-local after xor-1 shuffle.
// =======================================================================
template <int KW, int NCH, int FEAT, int LAYER>
__global__ void __launch_bounds__(512, 1)
lstm_mma(const float* __restrict__ xin, const float* __restrict__ Wih,
         const float* __restrict__ Whh, const float* __restrict__ bih,
         const float* __restrict__ bhh) {
    extern __shared__ char smem[];
    const int W_HI = 0, W_LO = KW * 512;
    const int A_HI = 2 * KW * 512, A_LO = A_HI + 16384;
    const int S_BIAS = A_LO + 16384;
    const uint32_t sbase = smem_u32(smem);

    const int tid = threadIdx.x, lane = tid & 31, wid = tid >> 5;
    const int rw = wid & 3, cg = wid >> 2;
    const int t4 = lane & 3, g8 = lane >> 2;
    const int r0 = rw * 16;
    const int rowb = blockIdx.x * 64;
    const int row_st = r0 + g8 + ((t4 & 1) ? 8 : 0);
    const int m = lane >> 3, q = lane & 7;
    const int t128 = cg * 32 + lane;   // index within row-group (128 threads)
    const int barid = rw + 1;

    // ---- stage W (permuted n=4j+type, split hi/lo) ----
    for (int idx = tid; idx < KW * 256; idx += 512) {
        int k = idx >> 8, n = idx & 255;
        int go = (n & 3) * 64 + (n >> 2);
        float w = (k < 64) ? Whh[go * 64 + k]
                           : ((k - 64 < FEAT) ? Wih[go * FEAT + (k - 64)] : 0.f);
        uint32_t hi, lo;
        bfsplit(w, hi, lo);
        uint32_t o = offW(k, n);
        *(uint16_t*)(smem + W_HI + o) = (uint16_t)hi;
        *(uint16_t*)(smem + W_LO + o) = (uint16_t)lo;
    }
    for (int i = tid; i < 2048; i += 512) ((uint4*)(smem + A_HI))[i] = make_uint4(0, 0, 0, 0);
    if (tid < 256) {
        int go = (tid & 3) * 64 + (tid >> 2);
        ((float*)(smem + S_BIAS))[tid] = bih[go] + bhh[go];
    }
    __syncthreads();

    // group-local x staging (rows r0..r0+15 only)
    int xrow = 0, xd = 0;
    if (LAYER == 0) { xrow = r0 + t128 / 6; xd = t128 - (t128 / 6) * 6; }
    const int hrow = r0 + (t128 >> 3);       // L1: row for h0 staging
    const int hkb = 64 + (t128 & 7) * 8;     // L1: k base
    float xf = 0.f;
    uint32_t xw[8];

    auto pfx = [&](int t) {
        if (LAYER == 0) {
            if (t128 < 96) xf = xin[((size_t)(rowb + xrow) * TT + t) * 6 + xd];
        } else {
            const uint32_t* p = g_hs0 + ((size_t)t * NROWS + rowb + hrow) * 64 + (t128 & 7) * 8;
            *(uint4*)&xw[0] = *(const uint4*)p;
            *(uint4*)&xw[4] = *(const uint4*)(p + 4);
        }
    };
    auto stx = [&]() {
        if (LAYER == 0) {
            if (t128 < 96) {
                uint32_t hi, lo;
                bfsplit(xf, hi, lo);
                uint32_t o = offA(xrow, 64 + xd);
                *(uint16_t*)(smem + A_HI + o) = (uint16_t)hi;
                *(uint16_t*)(smem + A_LO + o) = (uint16_t)lo;
            }
        } else {
            uint32_t o = offA(hrow, hkb);
            *(uint4*)(smem + A_HI + o) =
                make_uint4(prmt(xw[0], xw[1], 0x5410), prmt(xw[2], xw[3], 0x5410),
                           prmt(xw[4], xw[5], 0x5410), prmt(xw[6], xw[7], 0x5410));
            *(uint4*)(smem + A_LO + o) =
                make_uint4(prmt(xw[0], xw[1], 0x7632), prmt(xw[2], xw[3], 0x7632),
                           prmt(xw[4], xw[5], 0x7632), prmt(xw[6], xw[7], 0x7632));
        }
    };

    pfx(0);
    stx();
    __syncthreads();

    float c[8];
    #pragma unroll
    for (int nt = 0; nt < 8; ++nt) c[nt] = 0.f;

    #pragma unroll 1
    for (int t = 0; t < TT; ++t) {
        float d[8][4];
        #pragma unroll
        for (int nt = 0; nt < 8; ++nt) {
            float2 b2 = *(const float2*)(smem + S_BIAS + (cg * 64 + nt * 8 + t4 * 2) * 4);
            d[nt][0] = b2.x; d[nt][1] = b2.y; d[nt][2] = b2.x; d[nt][3] = b2.y;
        }
        if (t < TT - 1) pfx(t + 1);  // LDG overlapped with MMA

        // ---- MMA phase (reads A rows r0..r0+15, static W) ----
        #pragma unroll
        for (int ch = 0; ch < NCH; ++ch) {
            int ar = r0 + (m & 1) * 8 + q;
            int ak = ch * 16 + (m >> 1) * 8;
            uint32_t ao = offA(ar, ak);
            uint32_t ahi[4], alo[4];
            ldsm4(ahi, sbase + A_HI + ao);
            ldsm4(alo, sbase + A_LO + ao);
            int bk = ch * 16 + (m & 1) * 8 + q;
            uint32_t bhi[16], blo[16];
            #pragma unroll
            for (int p = 0; p < 4; ++p) {
                uint32_t bo = offW(bk, cg * 64 + (2 * p + (m >> 1)) * 8);
                ldsm4t(&bhi[4 * p], sbase + W_HI + bo);
                ldsm4t(&blo[4 * p], sbase + W_LO + bo);
            }
            #pragma unroll
            for (int nt = 0; nt < 8; ++nt) mma16816(d[nt], ahi, &bhi[2 * nt]);
            #pragma unroll
            for (int nt = 0; nt < 8; ++nt) mma16816(d[nt], alo, &bhi[2 * nt]);
            #pragma unroll
            for (int nt = 0; nt < 8; ++nt) mma16816(d[nt], ahi, &blo[2 * nt]);
        }
        barg(barid);  // group's A reads done before group rewrites its rows

        // ---- cell phase (tanh.approx) ----
        float hf[8];
        uint32_t w0a[8], w1a[8];
        #pragma unroll
        for (int nt = 0; nt < 8; ++nt) {
            float e0 = __shfl_xor_sync(0xffffffffu, d[nt][0], 1);
            float e1 = __shfl_xor_sync(0xffffffffu, d[nt][1], 1);
            float e2 = __shfl_xor_sync(0xffffffffu, d[nt][2], 1);
            float e3 = __shfl_xor_sync(0xffffffffu, d[nt][3], 1);
            float iv, fv, gv, ov;
            if (t4 & 1) { iv = e2; fv = e3; gv = d[nt][2]; ov = d[nt][3]; }
            else        { iv = d[nt][0]; fv = d[nt][1]; gv = e0; ov = e1; }
            float cc = siga(fv) * c[nt] + siga(iv) * tanha(gv);
            c[nt] = cc;
            float hh = siga(ov) * tanha(cc);
            hf[nt] = hh;
            uint32_t hi, lo;
            bfsplit(hh, hi, lo);
            uint32_t hpk = hi | (lo << 16);
            uint32_t rv = __shfl_xor_sync(0xffffffffu, hpk, 2);
            w0a[nt] = (t4 & 2) ? rv : hpk;   // j even
            w1a[nt] = (t4 & 2) ? hpk : rv;   // j odd
        }
        const int ntb = (t4 & 2) ? 4 : 0;
        const int kb = cg * 16 + ntb * 2;
        if (t < TT - 1) {
            uint32_t o = offA(row_st, kb);
            *(uint2*)(smem + A_HI + o) =
                make_uint2(prmt(w0a[ntb], w1a[ntb], 0x5410), prmt(w0a[ntb + 1], w1a[ntb + 1], 0x5410));
            *(uint2*)(smem + A_HI + o + 8) =
                make_uint2(prmt(w0a[ntb + 2], w1a[ntb + 2], 0x5410), prmt(w0a[ntb + 3], w1a[ntb + 3], 0x5410));
            *(uint2*)(smem + A_LO + o) =
                make_uint2(prmt(w0a[ntb], w1a[ntb], 0x7632), prmt(w0a[ntb + 1], w1a[ntb + 1], 0x7632));
            *(uint2*)(smem + A_LO + o + 8) =
                make_uint2(prmt(w0a[ntb + 2], w1a[ntb + 2], 0x7632), prmt(w0a[ntb + 3], w1a[ntb + 3], 0x7632));
            stx();
        }
        if (LAYER == 0) {
            uint32_t* dst = g_hs0 + ((size_t)t * NROWS + rowb + row_st) * 64 + kb;
            *(uint4*)dst = make_uint4(w0a[ntb], w1a[ntb], w0a[ntb + 1], w1a[ntb + 1]);
            *(uint4*)(dst + 4) = make_uint4(w0a[ntb + 2], w1a[ntb + 2], w0a[ntb + 3], w1a[ntb + 3]);
        } else if (t == TT - 1) {
            #pragma unroll
            for (int nt = 0; nt < 8; ++nt)
                g_hlast[(rowb + row_st) * 64 + cg * 16 + 2 * nt + (t4 >> 1)] = hf[nt];
        }
        barg(barid);  // group's writes visible before next MMA phase
    }
}

// =======================================================================
// GAT prep + O(N) attention + head (passing versions, unchanged)
// =======================================================================
__global__ void prep1(const float* __restrict__ Wt, const float* __restrict__ bt,
                      const float* __restrict__ a) {
    int tid = threadIdx.x;
    if (tid < 64) {
        float v = 0.f;
        for (int g = 0; g < 64; ++g) v += Wt[g * 64 + tid] * a[g];
        g_v1[tid] = v;
    } else if (tid < 128) {
        int k = tid - 64;
        float v = 0.f;
        for (int g = 0; g < 64; ++g) v += Wt[g * 64 + k] * a[64 + g];
        g_v2[k] = v;
    }
    if (tid == 0) {
        float c = 0.f;
        for (int g = 0; g < 64; ++g) c += bt[g] * a[g];
        g_c12[0] = c;
    }
    if (tid == 1) {
        float c = 0.f;
        for (int g = 0; g < 64; ++g) c += bt[g] * a[64 + g];
        g_c12[1] = c;
    }
}

__global__ void prep2() {
    int lane = threadIdx.x & 31, w = threadIdx.x >> 5;
    int r = blockIdx.x * 8 + w;
    float l0 = g_hlast[r * 64 + lane], l1 = g_hlast[r * 64 + 32 + lane];
    float p1 = l0 * g_v1[lane] + l1 * g_v1[lane + 32];
    float p2 = l0 * g_v2[lane] + l1 * g_v2[lane + 32];
    #pragma unroll
    for (int o = 16; o; o >>= 1) {
        p1 += __shfl_xor_sync(0xffffffffu, p1, o);
        p2 += __shfl_xor_sync(0xffffffffu, p2, o);
    }
    if (lane == 0) {
        g_s1[r] = p1 + g_c12[0];
        g_s2[r] = p2 + g_c12[1];
    }
}

__global__ void __launch_bounds__(1024, 1) sort_kernel() {
    extern __shared__ char sraw[];
    float* k = (float*)sraw;
    int* v = (int*)(sraw + NROWS * 4);
    int tid = threadIdx.x;
    for (int i = tid; i < NROWS; i += 1024) { k[i] = g_s1[i]; v[i] = i; }
    for (int size = 2; size <= NROWS; size <<= 1) {
        for (int stride = size >> 1; stride > 0; stride >>= 1) {
            __syncthreads();
            #pragma unroll
            for (int e = 0; e < NROWS / 1024; ++e) {
                int i = e * 1024 + tid;
                int j = i ^ stride;
                if (j > i) {
                    bool up = ((i & size) == 0);
                    float ki = k[i], kj = k[j];
                    if ((ki > kj) == up) {
                        k[i] = kj; k[j] = ki;
                        int t = v[i]; v[i] = v[j]; v[j] = t;
                    }
                }
            }
        }
    }
    __syncthreads();
    for (int i = tid; i < NROWS; i += 1024) { g_s1sorted[i] = k[i]; g_sidx[i] = v[i]; }
}

__global__ void scan1() {
    __shared__ float sA[64], sB[64];
    __shared__ int sI[64];
    int c = blockIdx.x, tid = threadIdx.x;
    if (tid < 64) {
        float smax = g_s1sorted[NROWS - 1];
        float key = g_s1sorted[c * 64 + tid];
        float A = __expf(key - smax);
        float B = __expf(0.01f * (key - smax));
        sA[tid] = A; sB[tid] = B;
        sI[tid] = g_sidx[c * 64 + tid];
        g_A[c * 64 + tid] = A;
        g_B[c * 64 + tid] = B;
    }
    __syncthreads();
    if (tid <= 64) {
        float sa = 0.f, sb = 0.f;
        #pragma unroll 4
        for (int mq = 0; mq < 64; ++mq) {
            float xv = (tid < 64) ? g_hlast[sI[mq] * 64 + tid] : 1.f;
            sa += sA[mq] * xv;
            sb += sB[mq] * xv;
        }
        g_chunkA[c * 65 + tid] = sa;
        g_chunkB[c * 65 + tid] = sb;
    }
}

__global__ void scan2() {
    __shared__ float bufB[NCHUNK], bufA[NCHUNK];
    int d = blockIdx.x;
    int c = threadIdx.x;
    float origB = g_chunkB[c * 65 + d];
    float origA = g_chunkA[c * 65 + d];
    bufB[c] = origB;
    bufA[NCHUNK - 1 - c] = origA;
    __syncthreads();
    #pragma unroll
    for (int off = 1; off < NCHUNK; off <<= 1) {
        float tb = (c >= off) ? bufB[c - off] : 0.f;
        float ta = (c >= off) ? bufA[c - off] : 0.f;
        __syncthreads();
        bufB[c] += tb;
        bufA[c] += ta;
        __syncthreads();
    }
    g_chunkB[c * 65 + d] = bufB[c] - origB;
    g_chunkA[c * 65 + d] = bufA[NCHUNK - 1 - c] - origA;
}

__global__ void scan3() {
    __shared__ float sA[64], sB[64];
    __shared__ int sI[64];
    int c = blockIdx.x, tid = threadIdx.x;
    if (tid < 64) {
        sA[tid] = g_A[c * 64 + tid];
        sB[tid] = g_B[c * 64 + tid];
        sI[tid] = g_sidx[c * 64 + tid];
    }
    __syncthreads();
    if (tid <= 64) {
        int d = tid;
        float run = g_chunkB[c * 65 + d];
        #pragma unroll 4
        for (int mq = 0; mq < 64; ++mq) {
            size_t kk = (size_t)(c * 64 + mq);
            g_preB[kk * 65 + d] = run;
            float xv = (d < 64) ? g_hlast[sI[mq] * 64 + d] : 1.f;
            run += sB[mq] * xv;
        }
        if (c == NCHUNK - 1) g_preB[(size_t)NROWS * 65 + d] = run;
        float runA = g_chunkA[c * 65 + d];
        #pragma unroll 4
        for (int mq = 63; mq >= 0; --mq) {
            float xv = (d < 64) ? g_hlast[sI[mq] * 64 + d] : 1.f;
            runA += sA[mq] * xv;
            g_suffA[(size_t)(c * 64 + mq) * 65 + d] = runA;
        }
        if (c == NCHUNK - 1) g_suffA[(size_t)NROWS * 65 + d] = 0.f;
    }
}

__global__ void __launch_bounds__(256)
final_kernel(const float* __restrict__ Wfc, const float* __restrict__ bfc,
             const float* __restrict__ Wout, const float* __restrict__ bout,
             float* __restrict__ out) {
    __shared__ float sWfcT[64 * 65];
    __shared__ float sWo[64], sBfc[64];
    __shared__ float sZ[8][64];
    int tid = threadIdx.x;
    for (int idx = tid; idx < 4096; idx += 256) {
        int cc = idx >> 6, kq = idx & 63;
        sWfcT[kq * 65 + cc] = Wfc[idx];
    }
    if (tid < 64) { sWo[tid] = Wout[tid]; sBfc[tid] = bfc[tid]; }
    __syncthreads();

    int wy = tid >> 5, l = tid & 31;
    int i = blockIdx.x * 8 + wy;
    float smax = g_s1sorted[NROWS - 1];
    float s2 = g_s2[i];
    float thr = -s2;

    int kk = 0;
    #pragma unroll
    for (int st = 4096; st > 0; st >>= 1)
        if (kk + st <= NROWS && g_s1sorted[kk + st - 1] <= thr) kk += st;

    float u = s2 + smax;
    float fA, fB;
    if (u > 0.f) { fA = 1.f;               fB = __expf(-0.99f * u); }
    else         { fA = __expf(0.99f * u); fB = 1.f; }

    const float* suff = &g_suffA[(size_t)kk * 65];
    const float* pre  = &g_preB[(size_t)kk * 65];
    float inv = __fdividef(1.f, fA * suff[64] + fB * pre[64]);
    #pragma unroll
    for (int h = 0; h < 2; ++h) {
        int d = l + h * 32;
        sZ[wy][d] = (fA * suff[d] + fB * pre[d]) * inv + g_hlast[i * 64 + d];
    }
    __syncwarp();

    float yp = 0.f;
    #pragma unroll
    for (int h = 0; h < 2; ++h) {
        int c = l + h * 32;
        float dot = sBfc[c];
        #pragma unroll 16
        for (int kq = 0; kq < 64; ++kq) dot += sZ[wy][kq] * sWfcT[kq * 65 + c];
        dot = dot > 0.f ? dot : 0.01f * dot;
        yp += dot * sWo[c];
    }
    #pragma unroll
    for (int o = 16; o; o >>= 1) yp += __shfl_xor_sync(0xffffffffu, yp, o);
    if (l == 0) out[i] = yp + bout[0];
}

// =======================================================================
extern "C" void kernel_launch(void* const* d_in, const int* in_sizes, int n_in,
                              void* d_out, int out_size) {
    const float* x    = (const float*)d_in[0];
    const float* Wih0 = (const float*)d_in[1];
    const float* Whh0 = (const float*)d_in[2];
    const float* bih0 = (const float*)d_in[3];
    const float* bhh0 = (const float*)d_in[4];
    const float* Wih1 = (const float*)d_in[5];
    const float* Whh1 = (const float*)d_in[6];
    const float* bih1 = (const float*)d_in[7];
    const float* bhh1 = (const float*)d_in[8];
    const float* Wt   = (const float*)d_in[9];
    const float* bt   = (const float*)d_in[10];
    const float* a    = (const float*)d_in[11];
    const float* Wfc  = (const float*)d_in[12];
    const float* bfc  = (const float*)d_in[13];
    const float* Wout = (const float*)d_in[14];
    const float* bout = (const float*)d_in[15];
    float* out = (float*)d_out;

    const int SM_L0 = 80 * 1024 + 33792;
    const int SM_L1 = 128 * 1024 + 33792;
    const int SM_SORT = NROWS * 8;

    cudaFuncSetAttribute(lstm_mma<80, 5, 6, 0>, cudaFuncAttributeMaxDynamicSharedMemorySize, SM_L0);
    cudaFuncSetAttribute(lstm_mma<128, 8, 64, 1>, cudaFuncAttributeMaxDynamicSharedMemorySize, SM_L1);
    cudaFuncSetAttribute(sort_kernel, cudaFuncAttributeMaxDynamicSharedMemorySize, SM_SORT);

    lstm_mma<80, 5, 6, 0><<<NROWS / 64, 512, SM_L0>>>(x, Wih0, Whh0, bih0, bhh0);
    lstm_mma<128, 8, 64, 1><<<NROWS / 64, 512, SM_L1>>>(x, Wih1, Whh1, bih1, bhh1);
    prep1<<<1, 128>>>(Wt, bt, a);
    prep2<<<NROWS / 8, 256>>>();
    sort_kernel<<<1, 1024, SM_SORT>>>();
    scan1<<<NCHUNK, 128>>>();
    scan2<<<65, NCHUNK>>>();
    scan3<<<NCHUNK, 128>>>();
    final_kernel<<<NROWS / 8, 256>>>(Wfc, bfc, Wout, bout, out);
}

// round 8
// speedup vs baseline: 2.7977x; 1.0309x over previous
#include <cuda_runtime.h>
#include <cuda_bf16.h>
#include <math.h>
#include <stdint.h>

#define NROWS 8192
#define TT    60
#define NCHUNK 128

// -------- device scratch --------
__device__ uint32_t g_hs0[(size_t)TT * NROWS * 64];  // L0 h, packed bf16 (hi | lo<<16)
__device__ float g_hlast[NROWS * 64];
__device__ float g_s1[NROWS];
__device__ float g_s2[NROWS];
__device__ float g_v1[64];
__device__ float g_v2[64];
__device__ float g_c12[2];
__device__ float g_s1sorted[NROWS];
__device__ int   g_sidx[NROWS];
__device__ float g_A[NROWS];
__device__ float g_B[NROWS];
__device__ float g_chunkA[NCHUNK * 65];
__device__ float g_chunkB[NCHUNK * 65];
__device__ float g_preB[(size_t)(NROWS + 1) * 65];
__device__ float g_suffA[(size_t)(NROWS + 1) * 65];

__device__ __forceinline__ float sigf(float x) { return __fdividef(1.f, 1.f + __expf(-x)); }
__device__ __forceinline__ float tanha(float x) {
    float r;
    asm("tanh.approx.f32 %0, %1;" : "=f"(r) : "f"(x));
    return r;
}
__device__ __forceinline__ float siga(float x) { return fmaf(tanha(0.5f * x), 0.5f, 0.5f); }

// -------- warp-MMA helpers (baseline sm_80+ ISA) --------
__device__ __forceinline__ uint32_t smem_u32(const void* p) {
    uint32_t a;
    asm("{ .reg .u64 t; cvta.to.shared.u64 t, %1; cvt.u32.u64 %0, t; }" : "=r"(a) : "l"(p));
    return a;
}
__device__ __forceinline__ void barg(int id) {
    asm volatile("bar.sync %0, 128;" :: "r"(id) : "memory");
}
__device__ __forceinline__ void ldsm4(uint32_t* r, uint32_t a) {
    asm volatile("ldmatrix.sync.aligned.m8n8.x4.shared.b16 {%0,%1,%2,%3}, [%4];"
                 : "=r"(r[0]), "=r"(r[1]), "=r"(r[2]), "=r"(r[3]) : "r"(a));
}
__device__ __forceinline__ void ldsm4t(uint32_t* r, uint32_t a) {
    asm volatile("ldmatrix.sync.aligned.m8n8.x4.trans.shared.b16 {%0,%1,%2,%3}, [%4];"
                 : "=r"(r[0]), "=r"(r[1]), "=r"(r[2]), "=r"(r[3]) : "r"(a));
}
__device__ __forceinline__ void mma16816(float* d, const uint32_t* a, const uint32_t* b) {
    asm volatile(
        "mma.sync.aligned.m16n8k16.row.col.f32.bf16.bf16.f32 "
        "{%0,%1,%2,%3}, {%4,%5,%6,%7}, {%8,%9}, {%0,%1,%2,%3};"
        : "+f"(d[0]), "+f"(d[1]), "+f"(d[2]), "+f"(d[3])
        : "r"(a[0]), "r"(a[1]), "r"(a[2]), "r"(a[3]), "r"(b[0]), "r"(b[1]));
}
__device__ __forceinline__ uint32_t prmt(uint32_t a, uint32_t b, uint32_t s) {
    uint32_t r;
    asm("prmt.b32 %0, %1, %2, %3;" : "=r"(r) : "r"(a), "r"(b), "r"(s));
    return r;
}
__device__ __forceinline__ void bfsplit(float v, uint32_t& hi, uint32_t& lo) {
    __nv_bfloat16 h = __float2bfloat16(v);
    __nv_bfloat16 l = __float2bfloat16(v - __bfloat162float(h));
    hi = *(uint16_t*)&h;
    lo = *(uint16_t*)&l;
}
// A tile [64 rows][128 k] bf16, 256B/row, swizzled 16B chunks
__device__ __forceinline__ uint32_t offA(int r, int k) {
    int ck = k >> 3;
    return (uint32_t)(r * 256 + (((ck & 8) | ((ck ^ r) & 7)) << 4) + (k & 7) * 2);
}
// W tile [k][256 n] bf16, 512B/row
__device__ __forceinline__ uint32_t offW(int k, int n) {
    int cn = n >> 3;
    return (uint32_t)(k * 512 + (((cn & 24) | ((cn ^ k) & 7)) << 4) + (n & 7) * 2);
}

// =======================================================================
// HMMA LSTM: 128 blocks x 64 rows, 512 threads (16 warps).
// Warp decomposition: rw = wid>>2 (row-group), cg = wid&3 (col-group).
// => each SMSP (wid&3 fixed... scheduler = wid%4 = cg) hosts one warp of
// each row-group; groups sync on bar.sync(rw+1,128) and drift against
// each other WITHIN a scheduler, overlapping MMA / MUFU / LDSM phases.
// 3-MMA bf16 split; cell update register-local after xor-1 shuffle.
// =======================================================================
template <int KW, int NCH, int FEAT, int LAYER>
__global__ void __launch_bounds__(512, 1)
lstm_mma(const float* __restrict__ xin, const float* __restrict__ Wih,
         const float* __restrict__ Whh, const float* __restrict__ bih,
         const float* __restrict__ bhh) {
    extern __shared__ char smem[];
    const int W_HI = 0, W_LO = KW * 512;
    const int A_HI = 2 * KW * 512, A_LO = A_HI + 16384;
    const int S_BIAS = A_LO + 16384;
    const uint32_t sbase = smem_u32(smem);

    const int tid = threadIdx.x, lane = tid & 31, wid = tid >> 5;
    const int rw = wid >> 2, cg = wid & 3;     // <-- swapped vs R7
    const int t4 = lane & 3, g8 = lane >> 2;
    const int r0 = rw * 16;
    const int rowb = blockIdx.x * 64;
    const int row_st = r0 + g8 + ((t4 & 1) ? 8 : 0);
    const int m = lane >> 3, q = lane & 7;
    const int t128 = cg * 32 + lane;   // index within row-group (128 threads)
    const int barid = rw + 1;

    // ---- stage W (permuted n=4j+type, split hi/lo) ----
    for (int idx = tid; idx < KW * 256; idx += 512) {
        int k = idx >> 8, n = idx & 255;
        int go = (n & 3) * 64 + (n >> 2);
        float w = (k < 64) ? Whh[go * 64 + k]
                           : ((k - 64 < FEAT) ? Wih[go * FEAT + (k - 64)] : 0.f);
        uint32_t hi, lo;
        bfsplit(w, hi, lo);
        uint32_t o = offW(k, n);
        *(uint16_t*)(smem + W_HI + o) = (uint16_t)hi;
        *(uint16_t*)(smem + W_LO + o) = (uint16_t)lo;
    }
    for (int i = tid; i < 2048; i += 512) ((uint4*)(smem + A_HI))[i] = make_uint4(0, 0, 0, 0);
    if (tid < 256) {
        int go = (tid & 3) * 64 + (tid >> 2);
        ((float*)(smem + S_BIAS))[tid] = bih[go] + bhh[go];
    }
    __syncthreads();

    // group-local x staging (rows r0..r0+15 only)
    int xrow = 0, xd = 0;
    if (LAYER == 0) { xrow = r0 + t128 / 6; xd = t128 - (t128 / 6) * 6; }
    const int hrow = r0 + (t128 >> 3);       // L1: row for h0 staging
    const int hkb = 64 + (t128 & 7) * 8;     // L1: k base
    float xf = 0.f;
    uint32_t xw[8];

    auto pfx = [&](int t) {
        if (LAYER == 0) {
            if (t128 < 96) xf = xin[((size_t)(rowb + xrow) * TT + t) * 6 + xd];
        } else {
            const uint32_t* p = g_hs0 + ((size_t)t * NROWS + rowb + hrow) * 64 + (t128 & 7) * 8;
            *(uint4*)&xw[0] = *(const uint4*)p;
            *(uint4*)&xw[4] = *(const uint4*)(p + 4);
        }
    };
    auto stx = [&]() {
        if (LAYER == 0) {
            if (t128 < 96) {
                uint32_t hi, lo;
                bfsplit(xf, hi, lo);
                uint32_t o = offA(xrow, 64 + xd);
                *(uint16_t*)(smem + A_HI + o) = (uint16_t)hi;
                *(uint16_t*)(smem + A_LO + o) = (uint16_t)lo;
            }
        } else {
            uint32_t o = offA(hrow, hkb);
            *(uint4*)(smem + A_HI + o) =
                make_uint4(prmt(xw[0], xw[1], 0x5410), prmt(xw[2], xw[3], 0x5410),
                           prmt(xw[4], xw[5], 0x5410), prmt(xw[6], xw[7], 0x5410));
            *(uint4*)(smem + A_LO + o) =
                make_uint4(prmt(xw[0], xw[1], 0x7632), prmt(xw[2], xw[3], 0x7632),
                           prmt(xw[4], xw[5], 0x7632), prmt(xw[6], xw[7], 0x7632));
        }
    };

    pfx(0);
    stx();
    __syncthreads();

    float c[8];
    #pragma unroll
    for (int nt = 0; nt < 8; ++nt) c[nt] = 0.f;

    #pragma unroll 1
    for (int t = 0; t < TT; ++t) {
        float d[8][4];
        #pragma unroll
        for (int nt = 0; nt < 8; ++nt) {
            float2 b2 = *(const float2*)(smem + S_BIAS + (cg * 64 + nt * 8 + t4 * 2) * 4);
            d[nt][0] = b2.x; d[nt][1] = b2.y; d[nt][2] = b2.x; d[nt][3] = b2.y;
        }
        if (t < TT - 1) pfx(t + 1);  // LDG overlapped with MMA

        // ---- MMA phase (reads A rows r0..r0+15, static W) ----
        #pragma unroll
        for (int ch = 0; ch < NCH; ++ch) {
            int ar = r0 + (m & 1) * 8 + q;
            int ak = ch * 16 + (m >> 1) * 8;
            uint32_t ao = offA(ar, ak);
            uint32_t ahi[4], alo[4];
            ldsm4(ahi, sbase + A_HI + ao);
            ldsm4(alo, sbase + A_LO + ao);
            int bk = ch * 16 + (m & 1) * 8 + q;
            uint32_t bhi[16], blo[16];
            #pragma unroll
            for (int p = 0; p < 4; ++p) {
                uint32_t bo = offW(bk, cg * 64 + (2 * p + (m >> 1)) * 8);
                ldsm4t(&bhi[4 * p], sbase + W_HI + bo);
                ldsm4t(&blo[4 * p], sbase + W_LO + bo);
            }
            #pragma unroll
            for (int nt = 0; nt < 8; ++nt) mma16816(d[nt], ahi, &bhi[2 * nt]);
            #pragma unroll
            for (int nt = 0; nt < 8; ++nt) mma16816(d[nt], alo, &bhi[2 * nt]);
            #pragma unroll
            for (int nt = 0; nt < 8; ++nt) mma16816(d[nt], ahi, &blo[2 * nt]);
        }
        barg(barid);  // group's A reads done before group rewrites its rows

        // ---- cell phase (tanh.approx) ----
        float hf[8];
        uint32_t w0a[8], w1a[8];
        #pragma unroll
        for (int nt = 0; nt < 8; ++nt) {
            float e0 = __shfl_xor_sync(0xffffffffu, d[nt][0], 1);
            float e1 = __shfl_xor_sync(0xffffffffu, d[nt][1], 1);
            float e2 = __shfl_xor_sync(0xffffffffu, d[nt][2], 1);
            float e3 = __shfl_xor_sync(0xffffffffu, d[nt][3], 1);
            float iv, fv, gv, ov;
            if (t4 & 1) { iv = e2; fv = e3; gv = d[nt][2]; ov = d[nt][3]; }
            else        { iv = d[nt][0]; fv = d[nt][1]; gv = e0; ov = e1; }
            float cc = siga(fv) * c[nt] + siga(iv) * tanha(gv);
            c[nt] = cc;
            float hh = siga(ov) * tanha(cc);
            hf[nt] = hh;
            uint32_t hi, lo;
            bfsplit(hh, hi, lo);
            uint32_t hpk = hi | (lo << 16);
            uint32_t rv = __shfl_xor_sync(0xffffffffu, hpk, 2);
            w0a[nt] = (t4 & 2) ? rv : hpk;   // j even
            w1a[nt] = (t4 & 2) ? hpk : rv;   // j odd
        }
        const int ntb = (t4 & 2) ? 4 : 0;
        const int kb = cg * 16 + ntb * 2;
        if (t < TT - 1) {
            uint32_t o = offA(row_st, kb);
            *(uint2*)(smem + A_HI + o) =
                make_uint2(prmt(w0a[ntb], w1a[ntb], 0x5410), prmt(w0a[ntb + 1], w1a[ntb + 1], 0x5410));
            *(uint2*)(smem + A_HI + o + 8) =
                make_uint2(prmt(w0a[ntb + 2], w1a[ntb + 2], 0x5410), prmt(w0a[ntb + 3], w1a[ntb + 3], 0x5410));
            *(uint2*)(smem + A_LO + o) =
                make_uint2(prmt(w0a[ntb], w1a[ntb], 0x7632), prmt(w0a[ntb + 1], w1a[ntb + 1], 0x7632));
            *(uint2*)(smem + A_LO + o + 8) =
                make_uint2(prmt(w0a[ntb + 2], w1a[ntb + 2], 0x7632), prmt(w0a[ntb + 3], w1a[ntb + 3], 0x7632));
            stx();
        }
        if (LAYER == 0) {
            uint32_t* dst = g_hs0 + ((size_t)t * NROWS + rowb + row_st) * 64 + kb;
            *(uint4*)dst = make_uint4(w0a[ntb], w1a[ntb], w0a[ntb + 1], w1a[ntb + 1]);
            *(uint4*)(dst + 4) = make_uint4(w0a[ntb + 2], w1a[ntb + 2], w0a[ntb + 3], w1a[ntb + 3]);
        } else if (t == TT - 1) {
            #pragma unroll
            for (int nt = 0; nt < 8; ++nt)
                g_hlast[(rowb + row_st) * 64 + cg * 16 + 2 * nt + (t4 >> 1)] = hf[nt];
        }
        barg(barid);  // group's writes visible before next MMA phase
    }
}

// =======================================================================
// GAT prep + O(N) attention + head (passing versions, unchanged)
// =======================================================================
__global__ void prep1(const float* __restrict__ Wt, const float* __restrict__ bt,
                      const float* __restrict__ a) {
    int tid = threadIdx.x;
    if (tid < 64) {
        float v = 0.f;
        for (int g = 0; g < 64; ++g) v += Wt[g * 64 + tid] * a[g];
        g_v1[tid] = v;
    } else if (tid < 128) {
        int k = tid - 64;
        float v = 0.f;
        for (int g = 0; g < 64; ++g) v += Wt[g * 64 + k] * a[64 + g];
        g_v2[k] = v;
    }
    if (tid == 0) {
        float c = 0.f;
        for (int g = 0; g < 64; ++g) c += bt[g] * a[g];
        g_c12[0] = c;
    }
    if (tid == 1) {
        float c = 0.f;
        for (int g = 0; g < 64; ++g) c += bt[g] * a[64 + g];
        g_c12[1] = c;
    }
}

__global__ void prep2() {
    int lane = threadIdx.x & 31, w = threadIdx.x >> 5;
    int r = blockIdx.x * 8 + w;
    float l0 = g_hlast[r * 64 + lane], l1 = g_hlast[r * 64 + 32 + lane];
    float p1 = l0 * g_v1[lane] + l1 * g_v1[lane + 32];
    float p2 = l0 * g_v2[lane] + l1 * g_v2[lane + 32];
    #pragma unroll
    for (int o = 16; o; o >>= 1) {
        p1 += __shfl_xor_sync(0xffffffffu, p1, o);
        p2 += __shfl_xor_sync(0xffffffffu, p2, o);
    }
    if (lane == 0) {
        g_s1[r] = p1 + g_c12[0];
        g_s2[r] = p2 + g_c12[1];
    }
}

__global__ void __launch_bounds__(1024, 1) sort_kernel() {
    extern __shared__ char sraw[];
    float* k = (float*)sraw;
    int* v = (int*)(sraw + NROWS * 4);
    int tid = threadIdx.x;
    for (int i = tid; i < NROWS; i += 1024) { k[i] = g_s1[i]; v[i] = i; }
    for (int size = 2; size <= NROWS; size <<= 1) {
        for (int stride = size >> 1; stride > 0; stride >>= 1) {
            __syncthreads();
            #pragma unroll
            for (int e = 0; e < NROWS / 1024; ++e) {
                int i = e * 1024 + tid;
                int j = i ^ stride;
                if (j > i) {
                    bool up = ((i & size) == 0);
                    float ki = k[i], kj = k[j];
                    if ((ki > kj) == up) {
                        k[i] = kj; k[j] = ki;
                        int t = v[i]; v[i] = v[j]; v[j] = t;
                    }
                }
            }
        }
    }
    __syncthreads();
    for (int i = tid; i < NROWS; i += 1024) { g_s1sorted[i] = k[i]; g_sidx[i] = v[i]; }
}

__global__ void scan1() {
    __shared__ float sA[64], sB[64];
    __shared__ int sI[64];
    int c = blockIdx.x, tid = threadIdx.x;
    if (tid < 64) {
        float smax = g_s1sorted[NROWS - 1];
        float key = g_s1sorted[c * 64 + tid];
        float A = __expf(key - smax);
        float B = __expf(0.01f * (key - smax));
        sA[tid] = A; sB[tid] = B;
        sI[tid] = g_sidx[c * 64 + tid];
        g_A[c * 64 + tid] = A;
        g_B[c * 64 + tid] = B;
    }
    __syncthreads();
    if (tid <= 64) {
        float sa = 0.f, sb = 0.f;
        #pragma unroll 4
        for (int mq = 0; mq < 64; ++mq) {
            float xv = (tid < 64) ? g_hlast[sI[mq] * 64 + tid] : 1.f;
            sa += sA[mq] * xv;
            sb += sB[mq] * xv;
        }
        g_chunkA[c * 65 + tid] = sa;
        g_chunkB[c * 65 + tid] = sb;
    }
}

__global__ void scan2() {
    __shared__ float bufB[NCHUNK], bufA[NCHUNK];
    int d = blockIdx.x;
    int c = threadIdx.x;
    float origB = g_chunkB[c * 65 + d];
    float origA = g_chunkA[c * 65 + d];
    bufB[c] = origB;
    bufA[NCHUNK - 1 - c] = origA;
    __syncthreads();
    #pragma unroll
    for (int off = 1; off < NCHUNK; off <<= 1) {
        float tb = (c >= off) ? bufB[c - off] : 0.f;
        float ta = (c >= off) ? bufA[c - off] : 0.f;
        __syncthreads();
        bufB[c] += tb;
        bufA[c] += ta;
        __syncthreads();
    }
    g_chunkB[c * 65 + d] = bufB[c] - origB;
    g_chunkA[c * 65 + d] = bufA[NCHUNK - 1 - c] - origA;
}

__global__ void scan3() {
    __shared__ float sA[64], sB[64];
    __shared__ int sI[64];
    int c = blockIdx.x, tid = threadIdx.x;
    if (tid < 64) {
        sA[tid] = g_A[c * 64 + tid];
        sB[tid] = g_B[c * 64 + tid];
        sI[tid] = g_sidx[c * 64 + tid];
    }
    __syncthreads();
    if (tid <= 64) {
        int d = tid;
        float run = g_chunkB[c * 65 + d];
        #pragma unroll 4
        for (int mq = 0; mq < 64; ++mq) {
            size_t kk = (size_t)(c * 64 + mq);
            g_preB[kk * 65 + d] = run;
            float xv = (d < 64) ? g_hlast[sI[mq] * 64 + d] : 1.f;
            run += sB[mq] * xv;
        }
        if (c == NCHUNK - 1) g_preB[(size_t)NROWS * 65 + d] = run;
        float runA = g_chunkA[c * 65 + d];
        #pragma unroll 4
        for (int mq = 63; mq >= 0; --mq) {
            float xv = (d < 64) ? g_hlast[sI[mq] * 64 + d] : 1.f;
            runA += sA[mq] * xv;
            g_suffA[(size_t)(c * 64 + mq) * 65 + d] = runA;
        }
        if (c == NCHUNK - 1) g_suffA[(size_t)NROWS * 65 + d] = 0.f;
    }
}

__global__ void __launch_bounds__(256)
final_kernel(const float* __restrict__ Wfc, const float* __restrict__ bfc,
             const float* __restrict__ Wout, const float* __restrict__ bout,
             float* __restrict__ out) {
    __shared__ float sWfcT[64 * 65];
    __shared__ float sWo[64], sBfc[64];
    __shared__ float sZ[8][64];
    int tid = threadIdx.x;
    for (int idx = tid; idx < 4096; idx += 256) {
        int cc = idx >> 6, kq = idx & 63;
        sWfcT[kq * 65 + cc] = Wfc[idx];
    }
    if (tid < 64) { sWo[tid] = Wout[tid]; sBfc[tid] = bfc[tid]; }
    __syncthreads();

    int wy = tid >> 5, l = tid & 31;
    int i = blockIdx.x * 8 + wy;
    float smax = g_s1sorted[NROWS - 1];
    float s2 = g_s2[i];
    float thr = -s2;

    int kk = 0;
    #pragma unroll
    for (int st = 4096; st > 0; st >>= 1)
        if (kk + st <= NROWS && g_s1sorted[kk + st - 1] <= thr) kk += st;

    float u = s2 + smax;
    float fA, fB;
    if (u > 0.f) { fA = 1.f;               fB = __expf(-0.99f * u); }
    else         { fA = __expf(0.99f * u); fB = 1.f; }

    const float* suff = &g_suffA[(size_t)kk * 65];
    const float* pre  = &g_preB[(size_t)kk * 65];
    float inv = __fdividef(1.f, fA * suff[64] + fB * pre[64]);
    #pragma unroll
    for (int h = 0; h < 2; ++h) {
        int d = l + h * 32;
        sZ[wy][d] = (fA * suff[d] + fB * pre[d]) * inv + g_hlast[i * 64 + d];
    }
    __syncwarp();

    float yp = 0.f;
    #pragma unroll
    for (int h = 0; h < 2; ++h) {
        int c = l + h * 32;
        float dot = sBfc[c];
        #pragma unroll 16
        for (int kq = 0; kq < 64; ++kq) dot += sZ[wy][kq] * sWfcT[kq * 65 + c];
        dot = dot > 0.f ? dot : 0.01f * dot;
        yp += dot * sWo[c];
    }
    #pragma unroll
    for (int o = 16; o; o >>= 1) yp += __shfl_xor_sync(0xffffffffu, yp, o);
    if (l == 0) out[i] = yp + bout[0];
}

// =======================================================================
extern "C" void kernel_launch(void* const* d_in, const int* in_sizes, int n_in,
                              void* d_out, int out_size) {
    const float* x    = (const float*)d_in[0];
    const float* Wih0 = (const float*)d_in[1];
    const float* Whh0 = (const float*)d_in[2];
    const float* bih0 = (const float*)d_in[3];
    const float* bhh0 = (const float*)d_in[4];
    const float* Wih1 = (const float*)d_in[5];
    const float* Whh1 = (const float*)d_in[6];
    const float* bih1 = (const float*)d_in[7];
    const float* bhh1 = (const float*)d_in[8];
    const float* Wt   = (const float*)d_in[9];
    const float* bt   = (const float*)d_in[10];
    const float* a    = (const float*)d_in[11];
    const float* Wfc  = (const float*)d_in[12];
    const float* bfc  = (const float*)d_in[13];
    const float* Wout = (const float*)d_in[14];
    const float* bout = (const float*)d_in[15];
    float* out = (float*)d_out;

    const int SM_L0 = 80 * 1024 + 33792;
    const int SM_L1 = 128 * 1024 + 33792;
    const int SM_SORT = NROWS * 8;

    cudaFuncSetAttribute(lstm_mma<80, 5, 6, 0>, cudaFuncAttributeMaxDynamicSharedMemorySize, SM_L0);
    cudaFuncSetAttribute(lstm_mma<128, 8, 64, 1>, cudaFuncAttributeMaxDynamicSharedMemorySize, SM_L1);
    cudaFuncSetAttribute(sort_kernel, cudaFuncAttributeMaxDynamicSharedMemorySize, SM_SORT);

    lstm_mma<80, 5, 6, 0><<<NROWS / 64, 512, SM_L0>>>(x, Wih0, Whh0, bih0, bhh0);
    lstm_mma<128, 8, 64, 1><<<NROWS / 64, 512, SM_L1>>>(x, Wih1, Whh1, bih1, bhh1);
    prep1<<<1, 128>>>(Wt, bt, a);
    prep2<<<NROWS / 8, 256>>>();
    sort_kernel<<<1, 1024, SM_SORT>>>();
    scan1<<<NCHUNK, 128>>>();
    scan2<<<65, NCHUNK>>>();
    scan3<<<NCHUNK, 128>>>();
    final_kernel<<<NROWS / 8, 256>>>(Wfc, bfc, Wout, bout, out);
}

// round 9
// speedup vs baseline: 2.9318x; 1.0479x over previous
#include <cuda_runtime.h>
#include <cuda_bf16.h>
#include <math.h>
#include <stdint.h>

#define NROWS 8192
#define TT    60
#define NCHUNK 128

// -------- device scratch --------
__device__ uint32_t g_hs0[(size_t)TT * NROWS * 64];  // L0 h, packed bf16 (hi | lo<<16)
__device__ float g_hlast[NROWS * 64];
__device__ float g_s1[NROWS];
__device__ float g_s2[NROWS];
__device__ float g_v1[64];
__device__ float g_v2[64];
__device__ float g_c12[2];
__device__ float g_s1sorted[NROWS];
__device__ int   g_sidx[NROWS];
__device__ float g_A[NROWS];
__device__ float g_B[NROWS];
__device__ float g_chunkA[NCHUNK * 65];
__device__ float g_chunkB[NCHUNK * 65];
__device__ float g_preB[(size_t)(NROWS + 1) * 65];
__device__ float g_suffA[(size_t)(NROWS + 1) * 65];

__device__ __forceinline__ float sigf(float x) { return __fdividef(1.f, 1.f + __expf(-x)); }
__device__ __forceinline__ float tanha(float x) {
    float r;
    asm("tanh.approx.f32 %0, %1;" : "=f"(r) : "f"(x));
    return r;
}
__device__ __forceinline__ float siga(float x) { return fmaf(tanha(0.5f * x), 0.5f, 0.5f); }

// -------- warp-MMA helpers (baseline sm_80+ ISA) --------
__device__ __forceinline__ uint32_t smem_u32(const void* p) {
    uint32_t a;
    asm("{ .reg .u64 t; cvta.to.shared.u64 t, %1; cvt.u32.u64 %0, t; }" : "=r"(a) : "l"(p));
    return a;
}
__device__ __forceinline__ void barg(int id) {
    asm volatile("bar.sync %0, 128;" :: "r"(id) : "memory");
}
__device__ __forceinline__ void ldsm4(uint32_t* r, uint32_t a) {
    asm volatile("ldmatrix.sync.aligned.m8n8.x4.shared.b16 {%0,%1,%2,%3}, [%4];"
                 : "=r"(r[0]), "=r"(r[1]), "=r"(r[2]), "=r"(r[3]) : "r"(a));
}
__device__ __forceinline__ void ldsm4t(uint32_t* r, uint32_t a) {
    asm volatile("ldmatrix.sync.aligned.m8n8.x4.trans.shared.b16 {%0,%1,%2,%3}, [%4];"
                 : "=r"(r[0]), "=r"(r[1]), "=r"(r[2]), "=r"(r[3]) : "r"(a));
}
__device__ __forceinline__ void mma16816(float* d, const uint32_t* a, const uint32_t* b) {
    asm volatile(
        "mma.sync.aligned.m16n8k16.row.col.f32.bf16.bf16.f32 "
        "{%0,%1,%2,%3}, {%4,%5,%6,%7}, {%8,%9}, {%0,%1,%2,%3};"
        : "+f"(d[0]), "+f"(d[1]), "+f"(d[2]), "+f"(d[3])
        : "r"(a[0]), "r"(a[1]), "r"(a[2]), "r"(a[3]), "r"(b[0]), "r"(b[1]));
}
__device__ __forceinline__ uint32_t prmt(uint32_t a, uint32_t b, uint32_t s) {
    uint32_t r;
    asm("prmt.b32 %0, %1, %2, %3;" : "=r"(r) : "r"(a), "r"(b), "r"(s));
    return r;
}
__device__ __forceinline__ void bfsplit(float v, uint32_t& hi, uint32_t& lo) {
    __nv_bfloat16 h = __float2bfloat16(v);
    __nv_bfloat16 l = __float2bfloat16(v - __bfloat162float(h));
    hi = *(uint16_t*)&h;
    lo = *(uint16_t*)&l;
}
// A tile [64 rows][128 k] bf16, 256B/row, swizzled 16B chunks
__device__ __forceinline__ uint32_t offA(int r, int k) {
    int ck = k >> 3;
    return (uint32_t)(r * 256 + (((ck & 8) | ((ck ^ r) & 7)) << 4) + (k & 7) * 2);
}
// W tile [k][256 n] bf16, 512B/row
__device__ __forceinline__ uint32_t offW(int k, int n) {
    int cn = n >> 3;
    return (uint32_t)(k * 512 + (((cn & 24) | ((cn ^ k) & 7)) << 4) + (n & 7) * 2);
}

// =======================================================================
// HMMA LSTM: 128 blocks x 64 rows, 512 threads (16 warps).
// rw = wid>>2 (row-group), cg = wid&3 (scheduler/col-group).
// A tile DOUBLE-BUFFERED (ping-pong per step): MMA reads buf p=t&1, cell
// stores h(t) + x(t+1) into buf 1-p -> ONE group barrier per step.
// Groups are fully independent on A (each reads only its 16 rows).
// 3-MMA bf16 split; cell update register-local after xor-1 shuffle.
// =======================================================================
template <int KW, int NCH, int FEAT, int LAYER>
__global__ void __launch_bounds__(512, 1)
lstm_mma(const float* __restrict__ xin, const float* __restrict__ Wih,
         const float* __restrict__ Whh, const float* __restrict__ bih,
         const float* __restrict__ bhh) {
    extern __shared__ char smem[];
    const int W_HI = 0, W_LO = KW * 512;
    const int A0 = 2 * KW * 512;           // two ping-pong buffers, 32KB each
    const int S_BIAS = A0 + 65536;
    const uint32_t sbase = smem_u32(smem);

    const int tid = threadIdx.x, lane = tid & 31, wid = tid >> 5;
    const int rw = wid >> 2, cg = wid & 3;
    const int t4 = lane & 3, g8 = lane >> 2;
    const int r0 = rw * 16;
    const int rowb = blockIdx.x * 64;
    const int row_st = r0 + g8 + ((t4 & 1) ? 8 : 0);
    const int m = lane >> 3, q = lane & 7;
    const int t128 = cg * 32 + lane;   // index within row-group (128 threads)
    const int barid = rw + 1;

    // ---- stage W (permuted n=4j+type, split hi/lo) ----
    for (int idx = tid; idx < KW * 256; idx += 512) {
        int k = idx >> 8, n = idx & 255;
        int go = (n & 3) * 64 + (n >> 2);
        float w = (k < 64) ? Whh[go * 64 + k]
                           : ((k - 64 < FEAT) ? Wih[go * FEAT + (k - 64)] : 0.f);
        uint32_t hi, lo;
        bfsplit(w, hi, lo);
        uint32_t o = offW(k, n);
        *(uint16_t*)(smem + W_HI + o) = (uint16_t)hi;
        *(uint16_t*)(smem + W_LO + o) = (uint16_t)lo;
    }
    // zero BOTH A buffers (64KB)
    for (int i = tid; i < 4096; i += 512) ((uint4*)(smem + A0))[i] = make_uint4(0, 0, 0, 0);
    if (tid < 256) {
        int go = (tid & 3) * 64 + (tid >> 2);
        ((float*)(smem + S_BIAS))[tid] = bih[go] + bhh[go];
    }
    __syncthreads();

    // group-local x staging (rows r0..r0+15 only)
    int xrow = 0, xd = 0;
    if (LAYER == 0) { xrow = r0 + t128 / 6; xd = t128 - (t128 / 6) * 6; }
    const int hrow = r0 + (t128 >> 3);       // L1: row for h0 staging
    const int hkb = 64 + (t128 & 7) * 8;     // L1: k base
    float xf = 0.f;
    uint32_t xw[8];

    auto pfx = [&](int t) {
        if (LAYER == 0) {
            if (t128 < 96) xf = xin[((size_t)(rowb + xrow) * TT + t) * 6 + xd];
        } else {
            const uint32_t* p = g_hs0 + ((size_t)t * NROWS + rowb + hrow) * 64 + (t128 & 7) * 8;
            *(uint4*)&xw[0] = *(const uint4*)p;
            *(uint4*)&xw[4] = *(const uint4*)(p + 4);
        }
    };
    auto stx = [&](int buf) {
        char* ah = smem + A0 + buf * 32768;
        char* al = ah + 16384;
        if (LAYER == 0) {
            if (t128 < 96) {
                uint32_t hi, lo;
                bfsplit(xf, hi, lo);
                uint32_t o = offA(xrow, 64 + xd);
                *(uint16_t*)(ah + o) = (uint16_t)hi;
                *(uint16_t*)(al + o) = (uint16_t)lo;
            }
        } else {
            uint32_t o = offA(hrow, hkb);
            *(uint4*)(ah + o) =
                make_uint4(prmt(xw[0], xw[1], 0x5410), prmt(xw[2], xw[3], 0x5410),
                           prmt(xw[4], xw[5], 0x5410), prmt(xw[6], xw[7], 0x5410));
            *(uint4*)(al + o) =
                make_uint4(prmt(xw[0], xw[1], 0x7632), prmt(xw[2], xw[3], 0x7632),
                           prmt(xw[4], xw[5], 0x7632), prmt(xw[6], xw[7], 0x7632));
        }
    };

    pfx(0);
    stx(0);
    __syncthreads();

    float c[8];
    #pragma unroll
    for (int nt = 0; nt < 8; ++nt) c[nt] = 0.f;

    #pragma unroll 1
    for (int t = 0; t < TT; ++t) {
        const int p = t & 1;
        const uint32_t abase = sbase + (uint32_t)(A0 + p * 32768);
        char* anh = smem + A0 + (1 - p) * 32768;   // next buffer (hi)
        char* anl = anh + 16384;

        float d[8][4];
        #pragma unroll
        for (int nt = 0; nt < 8; ++nt) {
            float2 b2 = *(const float2*)(smem + S_BIAS + (cg * 64 + nt * 8 + t4 * 2) * 4);
            d[nt][0] = b2.x; d[nt][1] = b2.y; d[nt][2] = b2.x; d[nt][3] = b2.y;
        }
        if (t < TT - 1) pfx(t + 1);  // LDG overlapped with MMA

        // ---- MMA phase (reads buf p, rows r0..r0+15, static W) ----
        #pragma unroll
        for (int ch = 0; ch < NCH; ++ch) {
            int ar = r0 + (m & 1) * 8 + q;
            int ak = ch * 16 + (m >> 1) * 8;
            uint32_t ao = offA(ar, ak);
            uint32_t ahi[4], alo[4];
            ldsm4(ahi, abase + ao);
            ldsm4(alo, abase + 16384 + ao);
            int bk = ch * 16 + (m & 1) * 8 + q;
            uint32_t bhi[16], blo[16];
            #pragma unroll
            for (int pp = 0; pp < 4; ++pp) {
                uint32_t bo = offW(bk, cg * 64 + (2 * pp + (m >> 1)) * 8);
                ldsm4t(&bhi[4 * pp], sbase + W_HI + bo);
                ldsm4t(&blo[4 * pp], sbase + W_LO + bo);
            }
            #pragma unroll
            for (int nt = 0; nt < 8; ++nt) mma16816(d[nt], ahi, &bhi[2 * nt]);
            #pragma unroll
            for (int nt = 0; nt < 8; ++nt) mma16816(d[nt], alo, &bhi[2 * nt]);
            #pragma unroll
            for (int nt = 0; nt < 8; ++nt) mma16816(d[nt], ahi, &blo[2 * nt]);
        }
        // NO barrier: stores go to the other buffer

        // ---- cell phase (tanh.approx) ----
        float hf[8];
        uint32_t w0a[8], w1a[8];
        #pragma unroll
        for (int nt = 0; nt < 8; ++nt) {
            float e0 = __shfl_xor_sync(0xffffffffu, d[nt][0], 1);
            float e1 = __shfl_xor_sync(0xffffffffu, d[nt][1], 1);
            float e2 = __shfl_xor_sync(0xffffffffu, d[nt][2], 1);
            float e3 = __shfl_xor_sync(0xffffffffu, d[nt][3], 1);
            float iv, fv, gv, ov;
            if (t4 & 1) { iv = e2; fv = e3; gv = d[nt][2]; ov = d[nt][3]; }
            else        { iv = d[nt][0]; fv = d[nt][1]; gv = e0; ov = e1; }
            float cc = siga(fv) * c[nt] + siga(iv) * tanha(gv);
            c[nt] = cc;
            float hh = siga(ov) * tanha(cc);
            hf[nt] = hh;
            uint32_t hi, lo;
            bfsplit(hh, hi, lo);
            uint32_t hpk = hi | (lo << 16);
            uint32_t rv = __shfl_xor_sync(0xffffffffu, hpk, 2);
            w0a[nt] = (t4 & 2) ? rv : hpk;   // j even
            w1a[nt] = (t4 & 2) ? hpk : rv;   // j odd
        }
        const int ntb = (t4 & 2) ? 4 : 0;
        const int kb = cg * 16 + ntb * 2;
        if (t < TT - 1) {
            uint32_t o = offA(row_st, kb);
            *(uint2*)(anh + o) =
                make_uint2(prmt(w0a[ntb], w1a[ntb], 0x5410), prmt(w0a[ntb + 1], w1a[ntb + 1], 0x5410));
            *(uint2*)(anh + o + 8) =
                make_uint2(prmt(w0a[ntb + 2], w1a[ntb + 2], 0x5410), prmt(w0a[ntb + 3], w1a[ntb + 3], 0x5410));
            *(uint2*)(anl + o) =
                make_uint2(prmt(w0a[ntb], w1a[ntb], 0x7632), prmt(w0a[ntb + 1], w1a[ntb + 1], 0x7632));
            *(uint2*)(anl + o + 8) =
                make_uint2(prmt(w0a[ntb + 2], w1a[ntb + 2], 0x7632), prmt(w0a[ntb + 3], w1a[ntb + 3], 0x7632));
            stx(1 - p);
        }
        if (LAYER == 0) {
            uint32_t* dst = g_hs0 + ((size_t)t * NROWS + rowb + row_st) * 64 + kb;
            *(uint4*)dst = make_uint4(w0a[ntb], w1a[ntb], w0a[ntb + 1], w1a[ntb + 1]);
            *(uint4*)(dst + 4) = make_uint4(w0a[ntb + 2], w1a[ntb + 2], w0a[ntb + 3], w1a[ntb + 3]);
        } else if (t == TT - 1) {
            #pragma unroll
            for (int nt = 0; nt < 8; ++nt)
                g_hlast[(rowb + row_st) * 64 + cg * 16 + 2 * nt + (t4 >> 1)] = hf[nt];
        }
        barg(barid);  // single per-step barrier: group's stores -> next reads
    }
}

// =======================================================================
// GAT prep + O(N) attention + head (passing versions, unchanged)
// =======================================================================
__global__ void prep1(const float* __restrict__ Wt, const float* __restrict__ bt,
                      const float* __restrict__ a) {
    int tid = threadIdx.x;
    if (tid < 64) {
        float v = 0.f;
        for (int g = 0; g < 64; ++g) v += Wt[g * 64 + tid] * a[g];
        g_v1[tid] = v;
    } else if (tid < 128) {
        int k = tid - 64;
        float v = 0.f;
        for (int g = 0; g < 64; ++g) v += Wt[g * 64 + k] * a[64 + g];
        g_v2[k] = v;
    }
    if (tid == 0) {
        float c = 0.f;
        for (int g = 0; g < 64; ++g) c += bt[g] * a[g];
        g_c12[0] = c;
    }
    if (tid == 1) {
        float c = 0.f;
        for (int g = 0; g < 64; ++g) c += bt[g] * a[64 + g];
        g_c12[1] = c;
    }
}

__global__ void prep2() {
    int lane = threadIdx.x & 31, w = threadIdx.x >> 5;
    int r = blockIdx.x * 8 + w;
    float l0 = g_hlast[r * 64 + lane], l1 = g_hlast[r * 64 + 32 + lane];
    float p1 = l0 * g_v1[lane] + l1 * g_v1[lane + 32];
    float p2 = l0 * g_v2[lane] + l1 * g_v2[lane + 32];
    #pragma unroll
    for (int o = 16; o; o >>= 1) {
        p1 += __shfl_xor_sync(0xffffffffu, p1, o);
        p2 += __shfl_xor_sync(0xffffffffu, p2, o);
    }
    if (lane == 0) {
        g_s1[r] = p1 + g_c12[0];
        g_s2[r] = p2 + g_c12[1];
    }
}

__global__ void __launch_bounds__(1024, 1) sort_kernel() {
    extern __shared__ char sraw[];
    float* k = (float*)sraw;
    int* v = (int*)(sraw + NROWS * 4);
    int tid = threadIdx.x;
    for (int i = tid; i < NROWS; i += 1024) { k[i] = g_s1[i]; v[i] = i; }
    for (int size = 2; size <= NROWS; size <<= 1) {
        for (int stride = size >> 1; stride > 0; stride >>= 1) {
            __syncthreads();
            #pragma unroll
            for (int e = 0; e < NROWS / 1024; ++e) {
                int i = e * 1024 + tid;
                int j = i ^ stride;
                if (j > i) {
                    bool up = ((i & size) == 0);
                    float ki = k[i], kj = k[j];
                    if ((ki > kj) == up) {
                        k[i] = kj; k[j] = ki;
                        int t = v[i]; v[i] = v[j]; v[j] = t;
                    }
                }
            }
        }
    }
    __syncthreads();
    for (int i = tid; i < NROWS; i += 1024) { g_s1sorted[i] = k[i]; g_sidx[i] = v[i]; }
}

__global__ void scan1() {
    __shared__ float sA[64], sB[64];
    __shared__ int sI[64];
    int c = blockIdx.x, tid = threadIdx.x;
    if (tid < 64) {
        float smax = g_s1sorted[NROWS - 1];
        float key = g_s1sorted[c * 64 + tid];
        float A = __expf(key - smax);
        float B = __expf(0.01f * (key - smax));
        sA[tid] = A; sB[tid] = B;
        sI[tid] = g_sidx[c * 64 + tid];
        g_A[c * 64 + tid] = A;
        g_B[c * 64 + tid] = B;
    }
    __syncthreads();
    if (tid <= 64) {
        float sa = 0.f, sb = 0.f;
        #pragma unroll 4
        for (int mq = 0; mq < 64; ++mq) {
            float xv = (tid < 64) ? g_hlast[sI[mq] * 64 + tid] : 1.f;
            sa += sA[mq] * xv;
            sb += sB[mq] * xv;
        }
        g_chunkA[c * 65 + tid] = sa;
        g_chunkB[c * 65 + tid] = sb;
    }
}

__global__ void scan2() {
    __shared__ float bufB[NCHUNK], bufA[NCHUNK];
    int d = blockIdx.x;
    int c = threadIdx.x;
    float origB = g_chunkB[c * 65 + d];
    float origA = g_chunkA[c * 65 + d];
    bufB[c] = origB;
    bufA[NCHUNK - 1 - c] = origA;
    __syncthreads();
    #pragma unroll
    for (int off = 1; off < NCHUNK; off <<= 1) {
        float tb = (c >= off) ? bufB[c - off] : 0.f;
        float ta = (c >= off) ? bufA[c - off] : 0.f;
        __syncthreads();
        bufB[c] += tb;
        bufA[c] += ta;
        __syncthreads();
    }
    g_chunkB[c * 65 + d] = bufB[c] - origB;
    g_chunkA[c * 65 + d] = bufA[NCHUNK - 1 - c] - origA;
}

__global__ void scan3() {
    __shared__ float sA[64], sB[64];
    __shared__ int sI[64];
    int c = blockIdx.x, tid = threadIdx.x;
    if (tid < 64) {
        sA[tid] = g_A[c * 64 + tid];
        sB[tid] = g_B[c * 64 + tid];
        sI[tid] = g_sidx[c * 64 + tid];
    }
    __syncthreads();
    if (tid <= 64) {
        int d = tid;
        float run = g_chunkB[c * 65 + d];
        #pragma unroll 4
        for (int mq = 0; mq < 64; ++mq) {
            size_t kk = (size_t)(c * 64 + mq);
            g_preB[kk * 65 + d] = run;
            float xv = (d < 64) ? g_hlast[sI[mq] * 64 + d] : 1.f;
            run += sB[mq] * xv;
        }
        if (c == NCHUNK - 1) g_preB[(size_t)NROWS * 65 + d] = run;
        float runA = g_chunkA[c * 65 + d];
        #pragma unroll 4
        for (int mq = 63; mq >= 0; --mq) {
            float xv = (d < 64) ? g_hlast[sI[mq] * 64 + d] : 1.f;
            runA += sA[mq] * xv;
            g_suffA[(size_t)(c * 64 + mq) * 65 + d] = runA;
        }
        if (c == NCHUNK - 1) g_suffA[(size_t)NROWS * 65 + d] = 0.f;
    }
}

__global__ void __launch_bounds__(256)
final_kernel(const float* __restrict__ Wfc, const float* __restrict__ bfc,
             const float* __restrict__ Wout, const float* __restrict__ bout,
             float* __restrict__ out) {
    __shared__ float sWfcT[64 * 65];
    __shared__ float sWo[64], sBfc[64];
    __shared__ float sZ[8][64];
    int tid = threadIdx.x;
    for (int idx = tid; idx < 4096; idx += 256) {
        int cc = idx >> 6, kq = idx & 63;
        sWfcT[kq * 65 + cc] = Wfc[idx];
    }
    if (tid < 64) { sWo[tid] = Wout[tid]; sBfc[tid] = bfc[tid]; }
    __syncthreads();

    int wy = tid >> 5, l = tid & 31;
    int i = blockIdx.x * 8 + wy;
    float smax = g_s1sorted[NROWS - 1];
    float s2 = g_s2[i];
    float thr = -s2;

    int kk = 0;
    #pragma unroll
    for (int st = 4096; st > 0; st >>= 1)
        if (kk + st <= NROWS && g_s1sorted[kk + st - 1] <= thr) kk += st;

    float u = s2 + smax;
    float fA, fB;
    if (u > 0.f) { fA = 1.f;               fB = __expf(-0.99f * u); }
    else         { fA = __expf(0.99f * u); fB = 1.f; }

    const float* suff = &g_suffA[(size_t)kk * 65];
    const float* pre  = &g_preB[(size_t)kk * 65];
    float inv = __fdividef(1.f, fA * suff[64] + fB * pre[64]);
    #pragma unroll
    for (int h = 0; h < 2; ++h) {
        int d = l + h * 32;
        sZ[wy][d] = (fA * suff[d] + fB * pre[d]) * inv + g_hlast[i * 64 + d];
    }
    __syncwarp();

    float yp = 0.f;
    #pragma unroll
    for (int h = 0; h < 2; ++h) {
        int c = l + h * 32;
        float dot = sBfc[c];
        #pragma unroll 16
        for (int kq = 0; kq < 64; ++kq) dot += sZ[wy][kq] * sWfcT[kq * 65 + c];
        dot = dot > 0.f ? dot : 0.01f * dot;
        yp += dot * sWo[c];
    }
    #pragma unroll
    for (int o = 16; o; o >>= 1) yp += __shfl_xor_sync(0xffffffffu, yp, o);
    if (l == 0) out[i] = yp + bout[0];
}

// =======================================================================
extern "C" void kernel_launch(void* const* d_in, const int* in_sizes, int n_in,
                              void* d_out, int out_size) {
    const float* x    = (const float*)d_in[0];
    const float* Wih0 = (const float*)d_in[1];
    const float* Whh0 = (const float*)d_in[2];
    const float* bih0 = (const float*)d_in[3];
    const float* bhh0 = (const float*)d_in[4];
    const float* Wih1 = (const float*)d_in[5];
    const float* Whh1 = (const float*)d_in[6];
    const float* bih1 = (const float*)d_in[7];
    const float* bhh1 = (const float*)d_in[8];
    const float* Wt   = (const float*)d_in[9];
    const float* bt   = (const float*)d_in[10];
    const float* a    = (const float*)d_in[11];
    const float* Wfc  = (const float*)d_in[12];
    const float* bfc  = (const float*)d_in[13];
    const float* Wout = (const float*)d_in[14];
    const float* bout = (const float*)d_in[15];
    float* out = (float*)d_out;

    const int SM_L0 = 2 * 80 * 512 + 65536 + 1024;    // 148480 B
    const int SM_L1 = 2 * 128 * 512 + 65536 + 1024;   // 197632 B
    const int SM_SORT = NROWS * 8;

    cudaFuncSetAttribute(lstm_mma<80, 5, 6, 0>, cudaFuncAttributeMaxDynamicSharedMemorySize, SM_L0);
    cudaFuncSetAttribute(lstm_mma<128, 8, 64, 1>, cudaFuncAttributeMaxDynamicSharedMemorySize, SM_L1);
    cudaFuncSetAttribute(sort_kernel, cudaFuncAttributeMaxDynamicSharedMemorySize, SM_SORT);

    lstm_mma<80, 5, 6, 0><<<NROWS / 64, 512, SM_L0>>>(x, Wih0, Whh0, bih0, bhh0);
    lstm_mma<128, 8, 64, 1><<<NROWS / 64, 512, SM_L1>>>(x, Wih1, Whh1, bih1, bhh1);
    prep1<<<1, 128>>>(Wt, bt, a);
    prep2<<<NROWS / 8, 256>>>();
    sort_kernel<<<1, 1024, SM_SORT>>>();
    scan1<<<NCHUNK, 128>>>();
    scan2<<<65, NCHUNK>>>();
    scan3<<<NCHUNK, 128>>>();
    final_kernel<<<NROWS / 8, 256>>>(Wfc, bfc, Wout, bout, out);
}